// round 3
// baseline (speedup 1.0000x reference)
#include <cuda_runtime.h>

// ---------------- problem constants ----------------
#define BB   2
#define LLEN 1024
#define DD   1024
#define EE   2048
#define SSZ  16
#define RRK  64
#define CKW  4
#define NLAY 4
#define VV   32000
#define BLR  (BB * LLEN)      // 2048 rows

// ---------------- scratch (device globals; no allocation allowed) ----------
__device__ float g_h[BLR * DD];          // residual stream        (8 MB)
__device__ float g_xn[BLR * DD];         // normed activations     (8 MB)
__device__ float g_uz[BLR * 2 * EE];     // W_in output            (32 MB)
__device__ float g_u[BLR * EE];          // post conv+silu         (16 MB)
__device__ float g_dbc[BLR * 96];        // dr|B|C                 (0.75 MB)
__device__ float g_delta[BLR * EE];      // softplus output        (16 MB)
__device__ float g_y[BLR * EE];          // gated scan output      (16 MB)
__device__ float g_wm[DD + 1];           // mean-over-S of W_rw, + mean b_rw

// ---------------- helpers ----------------
__device__ __forceinline__ float block_reduce_sum(float v) {
    __shared__ float red[8];
    __shared__ float tot;
    int lane = threadIdx.x & 31, wid = threadIdx.x >> 5;
#pragma unroll
    for (int o = 16; o; o >>= 1) v += __shfl_xor_sync(0xffffffffu, v, o);
    if (lane == 0) red[wid] = v;
    __syncthreads();
    if (wid == 0) {
        float w = (threadIdx.x < (blockDim.x >> 5)) ? red[threadIdx.x] : 0.f;
#pragma unroll
        for (int o = 4; o; o >>= 1) w += __shfl_xor_sync(0xffffffffu, w, o);
        if (threadIdx.x == 0) tot = w;
    }
    __syncthreads();
    return tot;
}

// ---------------- embedding ----------------
__global__ void embed_kernel(const int* __restrict__ x, const float* __restrict__ mask,
                             const float* __restrict__ emb, float* __restrict__ h) {
    int row = blockIdx.x;                     // 0..BLR-1
    int tok = x[row];
    float m = mask[row];
    const float4* src = reinterpret_cast<const float4*>(emb + (size_t)tok * DD);
    float4* dst = reinterpret_cast<float4*>(h + (size_t)row * DD);
    float4 v = src[threadIdx.x];              // 256 threads * 4 = 1024
    dst[threadIdx.x] = make_float4(v.x * m, v.y * m, v.z * m, v.w * m);
}

// ---------------- RMSNorm ----------------
__global__ void rmsnorm_kernel(const float* __restrict__ x, const float* __restrict__ w,
                               float* __restrict__ out) {
    int row = blockIdx.x;
    const float4* xr = reinterpret_cast<const float4*>(x + (size_t)row * DD);
    float4 v = xr[threadIdx.x];
    float ss = v.x * v.x + v.y * v.y + v.z * v.z + v.w * v.w;
    float tot = block_reduce_sum(ss);
    float scale = rsqrtf(tot / (float)DD + 1e-5f);
    float4 wv = reinterpret_cast<const float4*>(w)[threadIdx.x];
    float4 o = make_float4(v.x * scale * wv.x, v.y * scale * wv.y,
                           v.z * scale * wv.z, v.w * scale * wv.w);
    reinterpret_cast<float4*>(out + (size_t)row * DD)[threadIdx.x] = o;
}

// ---------------- generic fp32 GEMM, C[M,N] = A[M,K] @ B[K,N] ----------------
// EPI: 0 = store, 1 = accumulate (+=), 2 = softplus(v + bias[col])
// assumes K % 16 == 0, N % 4 == 0 (true for all shapes here)
template <int EPI>
__global__ void __launch_bounds__(256)
gemm_kernel(const float* __restrict__ A, const float* __restrict__ B,
            const float* __restrict__ bias, float* __restrict__ C,
            int M, int N, int Kd, int lda, int ldb, int ldc) {
    constexpr int BM = 128, BN = 64, BK = 16;
    __shared__ float As[BK][BM + 4];
    __shared__ float Bs[BK][BN];
    int tid = threadIdx.x;
    int bm = blockIdx.y * BM;
    int bn = blockIdx.x * BN;
    int trow = tid >> 4;     // 0..15 -> 8 rows each
    int tcol = tid & 15;     // 0..15 -> 4 cols each

    float acc[8][4];
#pragma unroll
    for (int i = 0; i < 8; i++)
#pragma unroll
        for (int j = 0; j < 4; j++) acc[i][j] = 0.f;

    for (int k0 = 0; k0 < Kd; k0 += BK) {
        // load A tile (128x16) transposed into As
#pragma unroll
        for (int i = 0; i < 2; i++) {
            int idx = tid * 2 + i;
            int r = idx >> 2, kq = idx & 3;
            float4 v = make_float4(0.f, 0.f, 0.f, 0.f);
            int arow = bm + r;
            if (arow < M)
                v = *reinterpret_cast<const float4*>(A + (size_t)arow * lda + k0 + kq * 4);
            As[kq * 4 + 0][r] = v.x;
            As[kq * 4 + 1][r] = v.y;
            As[kq * 4 + 2][r] = v.z;
            As[kq * 4 + 3][r] = v.w;
        }
        // load B tile (16x64)
        {
            int krow = tid >> 4, nq = tid & 15;
            float4 v = make_float4(0.f, 0.f, 0.f, 0.f);
            int bcol = bn + nq * 4;
            if (bcol < N)
                v = *reinterpret_cast<const float4*>(B + (size_t)(k0 + krow) * ldb + bcol);
            *reinterpret_cast<float4*>(&Bs[krow][nq * 4]) = v;
        }
        __syncthreads();
#pragma unroll
        for (int kk = 0; kk < BK; kk++) {
            float4 a0 = *reinterpret_cast<const float4*>(&As[kk][trow * 8]);
            float4 a1 = *reinterpret_cast<const float4*>(&As[kk][trow * 8 + 4]);
            float4 b0 = *reinterpret_cast<const float4*>(&Bs[kk][tcol * 4]);
            float ar[8] = {a0.x, a0.y, a0.z, a0.w, a1.x, a1.y, a1.z, a1.w};
            float br[4] = {b0.x, b0.y, b0.z, b0.w};
#pragma unroll
            for (int i = 0; i < 8; i++)
#pragma unroll
                for (int j = 0; j < 4; j++)
                    acc[i][j] = fmaf(ar[i], br[j], acc[i][j]);
        }
        __syncthreads();
    }

#pragma unroll
    for (int i = 0; i < 8; i++) {
        int cr = bm + trow * 8 + i;
        if (cr >= M) continue;
#pragma unroll
        for (int j = 0; j < 4; j++) {
            int cc = bn + tcol * 4 + j;
            if (cc >= N) continue;
            size_t off = (size_t)cr * ldc + cc;
            float v = acc[i][j];
            if (EPI == 0) {
                C[off] = v;
            } else if (EPI == 1) {
                C[off] += v;
            } else {
                v += bias[cc];
                C[off] = (v > 20.f) ? v : log1pf(__expf(v));
            }
        }
    }
}

// ---------------- causal depthwise conv (K=4) + bias + SiLU ----------------
__global__ void conv_silu_kernel(const float* __restrict__ uz, const float* __restrict__ cw,
                                 const float* __restrict__ cb, float* __restrict__ u) {
    int idx = blockIdx.x * blockDim.x + threadIdx.x;
    if (idx >= BLR * EE) return;
    int e = idx % EE;
    int bl = idx / EE;
    int l = bl % LLEN;
    const float* up = uz + (size_t)(bl - l) * (2 * EE) + e;   // batch base, col e
    float a = cb[e];
#pragma unroll
    for (int k = 0; k < CKW; k++) {
        int lp = l - (CKW - 1) + k;
        if (lp >= 0) a = fmaf(up[(size_t)lp * (2 * EE)], cw[e * CKW + k], a);
    }
    u[idx] = a / (1.f + __expf(-a));   // silu
}

// ---------------- selective scan: 2 channels per warp, fused gate ----------
__global__ void scan_kernel(const float* __restrict__ u, const float* __restrict__ delta,
                            const float* __restrict__ uz, const float* __restrict__ dbc,
                            const float* __restrict__ A_log, const float* __restrict__ Dsk,
                            float* __restrict__ y) {
    int w = (blockIdx.x * blockDim.x + threadIdx.x) >> 5;
    int lane = threadIdx.x & 31;
    if (w >= BB * EE / 2) return;
    int b = w / (EE / 2);
    int e = (w - b * (EE / 2)) * 2 + (lane >> 4);   // lanes 0-15: e0, 16-31: e0+1
    int s = lane & 15;

    float Ae = -__expf(A_log[e * SSZ + s]);
    float dskip = Dsk[e];
    const float* dptr = delta + (size_t)b * LLEN * EE + e;
    const float* uptr = u + (size_t)b * LLEN * EE + e;
    const float* zptr = uz + (size_t)b * LLEN * 2 * EE + EE + e;
    const float* bc = dbc + (size_t)b * LLEN * 96;
    float* yptr = y + (size_t)b * LLEN * EE + e;

    float hs = 0.f;
    for (int l = 0; l < LLEN; l++) {
        float dlt = dptr[(size_t)l * EE];
        float ul = uptr[(size_t)l * EE];
        float Bv = bc[l * 96 + RRK + s];
        float Cv = bc[l * 96 + RRK + SSZ + s];
        hs = fmaf(__expf(dlt * Ae), hs, (dlt * ul) * Bv);
        float p = hs * Cv;
        p += __shfl_xor_sync(0xffffffffu, p, 8);
        p += __shfl_xor_sync(0xffffffffu, p, 4);
        p += __shfl_xor_sync(0xffffffffu, p, 2);
        p += __shfl_xor_sync(0xffffffffu, p, 1);
        if ((lane & 15) == 0) {
            float z = zptr[(size_t)l * 2 * EE];
            float sz = z / (1.f + __expf(-z));
            yptr[(size_t)l * EE] = (p + ul * dskip) * sz;   // (y + u*D) * silu(z)
        }
    }
}

// ---------------- reward-weight reduction: wbar[d] = mean_s W_rw[d,s] -------
__global__ void wmean_kernel(const float* __restrict__ W_rw, const float* __restrict__ b_rw,
                             float* __restrict__ wm) {
    int d = blockIdx.x * blockDim.x + threadIdx.x;
    if (d < DD) {
        float sum = 0.f;
#pragma unroll
        for (int j = 0; j < SSZ; j++) sum += W_rw[d * SSZ + j];
        wm[d] = sum * (1.f / SSZ);
    }
    if (d == 0) {
        float sum = 0.f;
#pragma unroll
        for (int j = 0; j < SSZ; j++) sum += b_rw[j];
        wm[DD] = sum * (1.f / SSZ);
    }
}

// ---------------- per-row scale: h *= (h . wbar + bbar) ----------------
__global__ void rowscale_kernel(float* __restrict__ h, const float* __restrict__ wm) {
    int row = blockIdx.x;
    float4* hr = reinterpret_cast<float4*>(h + (size_t)row * DD);
    float4 hv = hr[threadIdx.x];
    float4 wv = reinterpret_cast<const float4*>(wm)[threadIdx.x];
    float dot = hv.x * wv.x + hv.y * wv.y + hv.z * wv.z + hv.w * wv.w;
    float s = block_reduce_sum(dot) + wm[DD];
    hr[threadIdx.x] = make_float4(hv.x * s, hv.y * s, hv.z * s, hv.w * s);
}

// ---------------- final LayerNorm ----------------
__global__ void ln_kernel(const float* __restrict__ h, const float* __restrict__ g,
                          const float* __restrict__ bta, float* __restrict__ out) {
    int row = blockIdx.x;
    const float4* hr = reinterpret_cast<const float4*>(h + (size_t)row * DD);
    float4 v = hr[threadIdx.x];
    float sm = v.x + v.y + v.z + v.w;
    float sq = v.x * v.x + v.y * v.y + v.z * v.z + v.w * v.w;
    float mu = block_reduce_sum(sm) / (float)DD;
    float var = block_reduce_sum(sq) / (float)DD - mu * mu;
    float inv = rsqrtf(var + 1e-5f);
    float4 gv = reinterpret_cast<const float4*>(g)[threadIdx.x];
    float4 bv = reinterpret_cast<const float4*>(bta)[threadIdx.x];
    float4 o = make_float4((v.x - mu) * inv * gv.x + bv.x,
                           (v.y - mu) * inv * gv.y + bv.y,
                           (v.z - mu) * inv * gv.z + bv.z,
                           (v.w - mu) * inv * gv.w + bv.w);
    reinterpret_cast<float4*>(out + (size_t)row * DD)[threadIdx.x] = o;
}

// ---------------- host orchestration ----------------
extern "C" void kernel_launch(void* const* d_in, const int* in_sizes, int n_in,
                              void* d_out, int out_size) {
    const int* x = (const int*)d_in[0];
    const float* mask = (const float*)d_in[1];
    const float* emb = (const float*)d_in[2];
    const float* norm_w = (const float*)d_in[3];
    const float* W_in = (const float*)d_in[4];
    const float* conv_w = (const float*)d_in[5];
    const float* conv_b = (const float*)d_in[6];
    const float* W_x = (const float*)d_in[7];
    const float* W_dt = (const float*)d_in[8];
    const float* b_dt = (const float*)d_in[9];
    const float* A_log = (const float*)d_in[10];
    const float* D_skip = (const float*)d_in[11];
    const float* W_out = (const float*)d_in[12];
    const float* W_rw = (const float*)d_in[13];
    const float* b_rw = (const float*)d_in[14];
    const float* ln_g = (const float*)d_in[15];
    const float* ln_b = (const float*)d_in[16];
    const float* head_W = (const float*)d_in[17];
    float* out = (float*)d_out;

    float *h_, *xn_, *uz_, *u_, *dbc_, *delta_, *y_, *wm_;
    cudaGetSymbolAddress((void**)&h_, g_h);
    cudaGetSymbolAddress((void**)&xn_, g_xn);
    cudaGetSymbolAddress((void**)&uz_, g_uz);
    cudaGetSymbolAddress((void**)&u_, g_u);
    cudaGetSymbolAddress((void**)&dbc_, g_dbc);
    cudaGetSymbolAddress((void**)&delta_, g_delta);
    cudaGetSymbolAddress((void**)&y_, g_y);
    cudaGetSymbolAddress((void**)&wm_, g_wm);

    embed_kernel<<<BLR, 256>>>(x, mask, emb, h_);

    for (int i = 0; i < NLAY; i++) {
        rmsnorm_kernel<<<BLR, 256>>>(h_, norm_w + (size_t)i * DD, xn_);

        // xn @ W_in  -> uz  (2048 x 1024 x 4096)
        {
            dim3 g((2 * EE + 63) / 64, BLR / 128);
            gemm_kernel<0><<<g, 256>>>(xn_, W_in + (size_t)i * DD * 2 * EE, nullptr, uz_,
                                       BLR, 2 * EE, DD, DD, 2 * EE, 2 * EE);
        }

        conv_silu_kernel<<<(BLR * EE) / 256, 256>>>(uz_, conv_w + (size_t)i * EE * CKW,
                                                    conv_b + (size_t)i * EE, u_);

        // u @ W_x -> dbc  (2048 x 2048 x 96)
        {
            dim3 g((96 + 63) / 64, BLR / 128);
            gemm_kernel<0><<<g, 256>>>(u_, W_x + (size_t)i * EE * 96, nullptr, dbc_,
                                       BLR, 96, EE, EE, 96, 96);
        }

        // delta = softplus(dr @ W_dt + b_dt)  (2048 x 64 x 2048)
        {
            dim3 g((EE + 63) / 64, BLR / 128);
            gemm_kernel<2><<<g, 256>>>(dbc_, W_dt + (size_t)i * RRK * EE,
                                       b_dt + (size_t)i * EE, delta_,
                                       BLR, EE, RRK, 96, EE, EE);
        }

        // selective scan + D skip + SiLU gate  -> y
        scan_kernel<<<(BB * EE / 2) * 32 / 256, 256>>>(u_, delta_, uz_, dbc_,
                                                       A_log + (size_t)i * EE * SSZ,
                                                       D_skip + (size_t)i * EE, y_);

        // h += y @ W_out  (2048 x 2048 x 1024)
        {
            dim3 g((DD + 63) / 64, BLR / 128);
            gemm_kernel<1><<<g, 256>>>(y_, W_out + (size_t)i * EE * DD, nullptr, h_,
                                       BLR, DD, EE, EE, DD, DD);
        }

        // reward-weight scaling: h *= mean_s(h @ W_rw + b_rw)
        wmean_kernel<<<DD / 256, 256>>>(W_rw + (size_t)i * DD * SSZ,
                                        b_rw + (size_t)i * SSZ, wm_);
        rowscale_kernel<<<BLR, 256>>>(h_, wm_);
    }

    ln_kernel<<<BLR, 256>>>(h_, ln_g, ln_b, xn_);

    // logits = xn @ head_W  (2048 x 1024 x 32000)
    {
        dim3 g((VV + 63) / 64, BLR / 128);
        gemm_kernel<0><<<g, 256>>>(xn_, head_W, nullptr, out,
                                   BLR, VV, DD, DD, VV, VV);
    }
}

// round 4
// speedup vs baseline: 1.3158x; 1.3158x over previous
#include <cuda_runtime.h>

// ---------------- problem constants ----------------
#define BB   2
#define LLEN 1024
#define DD   1024
#define EE   2048
#define SSZ  16
#define RRK  64
#define CKW  4
#define NLAY 4
#define VV   32000
#define BLR  (BB * LLEN)      // 2048 rows

// ---------------- scratch (device globals; no allocation allowed) ----------
__device__ float g_h[BLR * DD];          // residual stream        (8 MB)
__device__ float g_xn[BLR * DD];         // normed activations     (8 MB)
__device__ float g_uz[BLR * 2 * EE];     // W_in output            (32 MB)
__device__ float g_u[BLR * EE];          // post conv+silu         (16 MB)
__device__ float g_dbc[BLR * 96];        // dr|B|C                 (0.75 MB)
__device__ float g_delta[BLR * EE];      // softplus output        (16 MB)
__device__ float g_y[BLR * EE];          // gated scan output      (16 MB)
__device__ float g_wm[DD + 1];           // mean-over-S of W_rw, + mean b_rw

// ---------------- helpers ----------------
__device__ __forceinline__ float block_reduce_sum(float v) {
    __shared__ float red[8];
    __shared__ float tot;
    int lane = threadIdx.x & 31, wid = threadIdx.x >> 5;
#pragma unroll
    for (int o = 16; o; o >>= 1) v += __shfl_xor_sync(0xffffffffu, v, o);
    if (lane == 0) red[wid] = v;
    __syncthreads();
    if (wid == 0) {
        float w = (threadIdx.x < (blockDim.x >> 5)) ? red[threadIdx.x] : 0.f;
#pragma unroll
        for (int o = 4; o; o >>= 1) w += __shfl_xor_sync(0xffffffffu, w, o);
        if (threadIdx.x == 0) tot = w;
    }
    __syncthreads();
    return tot;
}

__device__ __forceinline__ unsigned cvt_tf32(float x) {
    unsigned r;
    asm("cvt.rna.tf32.f32 %0, %1;" : "=r"(r) : "f"(x));
    return r;
}

// ================= tf32 tensor-core GEMM =================
// C[M=2048, N] = A[2048, K] @ B[K, N], lda=K, ldb=ldc=N.
// Requires N % 128 == 0, K % 16 == 0 (true for all call sites).
// EPI: 0 = store, 1 = accumulate (+=)
template <int EPI>
__global__ void __launch_bounds__(256, 1)
tf32_gemm(const float* __restrict__ A, const float* __restrict__ B,
          float* __restrict__ C, int N, int Kd) {
    constexpr int BM = 128, BN = 128, BK = 16;
    constexpr int LDA = 136, LDB = 136;           // pad -> conflict-free frag loads
    __shared__ unsigned As[2][BK * LDA];          // [k][m], tf32 bits
    __shared__ unsigned Bs[2][BK * LDB];          // [k][n], tf32 bits

    int tid = threadIdx.x;
    int bm = blockIdx.y * BM;
    int bn = blockIdx.x * BN;
    int warp = tid >> 5, lane = tid & 31;
    int wm = (warp >> 2) * 64;                    // warp grid 2 (m) x 4 (n)
    int wn = (warp & 3) * 32;
    int gid = lane >> 2, tig = lane & 3;

    const float* Aptr = A + (size_t)bm * Kd;
    const float* Bptr = B + bn;

    float4 ra[2], rb[2];
    float acc[4][4][4];
#pragma unroll
    for (int mt = 0; mt < 4; mt++)
#pragma unroll
        for (int nt = 0; nt < 4; nt++)
#pragma unroll
            for (int q = 0; q < 4; q++) acc[mt][nt][q] = 0.f;

    int nk = Kd / BK;

    // ---- prologue load tile 0 ----
#pragma unroll
    for (int i = 0; i < 2; i++) {
        int idx = tid * 2 + i;
        ra[i] = *reinterpret_cast<const float4*>(Aptr + (size_t)(idx >> 2) * Kd + (idx & 3) * 4);
        rb[i] = *reinterpret_cast<const float4*>(Bptr + (size_t)(idx >> 5) * N + (idx & 31) * 4);
    }
    {
#pragma unroll
        for (int i = 0; i < 2; i++) {
            int idx = tid * 2 + i;
            int r = idx >> 2, kq = (idx & 3) * 4;
            As[0][(kq + 0) * LDA + r] = cvt_tf32(ra[i].x);
            As[0][(kq + 1) * LDA + r] = cvt_tf32(ra[i].y);
            As[0][(kq + 2) * LDA + r] = cvt_tf32(ra[i].z);
            As[0][(kq + 3) * LDA + r] = cvt_tf32(ra[i].w);
            int br = idx >> 5, nc = (idx & 31) * 4;
            unsigned* bp = &Bs[0][br * LDB + nc];
            bp[0] = cvt_tf32(rb[i].x);
            bp[1] = cvt_tf32(rb[i].y);
            bp[2] = cvt_tf32(rb[i].z);
            bp[3] = cvt_tf32(rb[i].w);
        }
    }
    __syncthreads();

    for (int kb = 0; kb < nk; kb++) {
        if (kb + 1 < nk) {
            int k0 = (kb + 1) * BK;
#pragma unroll
            for (int i = 0; i < 2; i++) {
                int idx = tid * 2 + i;
                ra[i] = *reinterpret_cast<const float4*>(Aptr + (size_t)(idx >> 2) * Kd + k0 + (idx & 3) * 4);
                rb[i] = *reinterpret_cast<const float4*>(Bptr + (size_t)(k0 + (idx >> 5)) * N + (idx & 31) * 4);
            }
        }
        int s = kb & 1;
#pragma unroll
        for (int ks = 0; ks < 2; ks++) {
            int kk = ks * 8 + tig;
            unsigned af[4][4], bf[4][2];
#pragma unroll
            for (int mt = 0; mt < 4; mt++) {
                int m = wm + mt * 16 + gid;
                af[mt][0] = As[s][kk * LDA + m];
                af[mt][1] = As[s][kk * LDA + m + 8];
                af[mt][2] = As[s][(kk + 4) * LDA + m];
                af[mt][3] = As[s][(kk + 4) * LDA + m + 8];
            }
#pragma unroll
            for (int nt = 0; nt < 4; nt++) {
                int n = wn + nt * 8 + gid;
                bf[nt][0] = Bs[s][kk * LDB + n];
                bf[nt][1] = Bs[s][(kk + 4) * LDB + n];
            }
#pragma unroll
            for (int mt = 0; mt < 4; mt++)
#pragma unroll
                for (int nt = 0; nt < 4; nt++) {
                    float* c = acc[mt][nt];
                    asm volatile(
                        "mma.sync.aligned.m16n8k8.row.col.f32.tf32.tf32.f32 "
                        "{%0,%1,%2,%3}, {%4,%5,%6,%7}, {%8,%9}, {%0,%1,%2,%3};"
                        : "+f"(c[0]), "+f"(c[1]), "+f"(c[2]), "+f"(c[3])
                        : "r"(af[mt][0]), "r"(af[mt][1]), "r"(af[mt][2]), "r"(af[mt][3]),
                          "r"(bf[nt][0]), "r"(bf[nt][1]));
                }
        }
        if (kb + 1 < nk) {
            int d = (kb + 1) & 1;
#pragma unroll
            for (int i = 0; i < 2; i++) {
                int idx = tid * 2 + i;
                int r = idx >> 2, kq = (idx & 3) * 4;
                As[d][(kq + 0) * LDA + r] = cvt_tf32(ra[i].x);
                As[d][(kq + 1) * LDA + r] = cvt_tf32(ra[i].y);
                As[d][(kq + 2) * LDA + r] = cvt_tf32(ra[i].z);
                As[d][(kq + 3) * LDA + r] = cvt_tf32(ra[i].w);
                int br = idx >> 5, nc = (idx & 31) * 4;
                unsigned* bp = &Bs[d][br * LDB + nc];
                bp[0] = cvt_tf32(rb[i].x);
                bp[1] = cvt_tf32(rb[i].y);
                bp[2] = cvt_tf32(rb[i].z);
                bp[3] = cvt_tf32(rb[i].w);
            }
        }
        __syncthreads();
    }

    // ---- epilogue ----
#pragma unroll
    for (int mt = 0; mt < 4; mt++) {
        int row = bm + wm + mt * 16 + gid;
#pragma unroll
        for (int nt = 0; nt < 4; nt++) {
            int col = bn + wn + nt * 8 + tig * 2;
            float* c0 = C + (size_t)row * N + col;
            float* c1 = C + (size_t)(row + 8) * N + col;
            if (EPI == 0) {
                c0[0] = acc[mt][nt][0];
                c0[1] = acc[mt][nt][1];
                c1[0] = acc[mt][nt][2];
                c1[1] = acc[mt][nt][3];
            } else {
                c0[0] += acc[mt][nt][0];
                c0[1] += acc[mt][nt][1];
                c1[0] += acc[mt][nt][2];
                c1[1] += acc[mt][nt][3];
            }
        }
    }
}

// ---------------- embedding ----------------
__global__ void embed_kernel(const int* __restrict__ x, const float* __restrict__ mask,
                             const float* __restrict__ emb, float* __restrict__ h) {
    int row = blockIdx.x;
    int tok = x[row];
    float m = mask[row];
    const float4* src = reinterpret_cast<const float4*>(emb + (size_t)tok * DD);
    float4* dst = reinterpret_cast<float4*>(h + (size_t)row * DD);
    float4 v = src[threadIdx.x];
    dst[threadIdx.x] = make_float4(v.x * m, v.y * m, v.z * m, v.w * m);
}

// ---------------- RMSNorm ----------------
__global__ void rmsnorm_kernel(const float* __restrict__ x, const float* __restrict__ w,
                               float* __restrict__ out) {
    int row = blockIdx.x;
    const float4* xr = reinterpret_cast<const float4*>(x + (size_t)row * DD);
    float4 v = xr[threadIdx.x];
    float ss = v.x * v.x + v.y * v.y + v.z * v.z + v.w * v.w;
    float tot = block_reduce_sum(ss);
    float scale = rsqrtf(tot / (float)DD + 1e-5f);
    float4 wv = reinterpret_cast<const float4*>(w)[threadIdx.x];
    float4 o = make_float4(v.x * scale * wv.x, v.y * scale * wv.y,
                           v.z * scale * wv.z, v.w * scale * wv.w);
    reinterpret_cast<float4*>(out + (size_t)row * DD)[threadIdx.x] = o;
}

// ---------------- generic fp32 GEMM (small shapes) ----------------
// EPI: 0 = store, 2 = softplus(v + bias[col])
template <int EPI>
__global__ void __launch_bounds__(256)
gemm_kernel(const float* __restrict__ A, const float* __restrict__ B,
            const float* __restrict__ bias, float* __restrict__ C,
            int M, int N, int Kd, int lda, int ldb, int ldc) {
    constexpr int BM = 128, BN = 64, BK = 16;
    __shared__ float As[BK][BM + 4];
    __shared__ float Bs[BK][BN];
    int tid = threadIdx.x;
    int bm = blockIdx.y * BM;
    int bn = blockIdx.x * BN;
    int trow = tid >> 4;
    int tcol = tid & 15;

    float acc[8][4];
#pragma unroll
    for (int i = 0; i < 8; i++)
#pragma unroll
        for (int j = 0; j < 4; j++) acc[i][j] = 0.f;

    for (int k0 = 0; k0 < Kd; k0 += BK) {
#pragma unroll
        for (int i = 0; i < 2; i++) {
            int idx = tid * 2 + i;
            int r = idx >> 2, kq = idx & 3;
            float4 v = make_float4(0.f, 0.f, 0.f, 0.f);
            int arow = bm + r;
            if (arow < M)
                v = *reinterpret_cast<const float4*>(A + (size_t)arow * lda + k0 + kq * 4);
            As[kq * 4 + 0][r] = v.x;
            As[kq * 4 + 1][r] = v.y;
            As[kq * 4 + 2][r] = v.z;
            As[kq * 4 + 3][r] = v.w;
        }
        {
            int krow = tid >> 4, nq = tid & 15;
            float4 v = make_float4(0.f, 0.f, 0.f, 0.f);
            int bcol = bn + nq * 4;
            if (bcol < N)
                v = *reinterpret_cast<const float4*>(B + (size_t)(k0 + krow) * ldb + bcol);
            *reinterpret_cast<float4*>(&Bs[krow][nq * 4]) = v;
        }
        __syncthreads();
#pragma unroll
        for (int kk = 0; kk < BK; kk++) {
            float4 a0 = *reinterpret_cast<const float4*>(&As[kk][trow * 8]);
            float4 a1 = *reinterpret_cast<const float4*>(&As[kk][trow * 8 + 4]);
            float4 b0 = *reinterpret_cast<const float4*>(&Bs[kk][tcol * 4]);
            float ar[8] = {a0.x, a0.y, a0.z, a0.w, a1.x, a1.y, a1.z, a1.w};
            float br[4] = {b0.x, b0.y, b0.z, b0.w};
#pragma unroll
            for (int i = 0; i < 8; i++)
#pragma unroll
                for (int j = 0; j < 4; j++)
                    acc[i][j] = fmaf(ar[i], br[j], acc[i][j]);
        }
        __syncthreads();
    }

#pragma unroll
    for (int i = 0; i < 8; i++) {
        int cr = bm + trow * 8 + i;
        if (cr >= M) continue;
#pragma unroll
        for (int j = 0; j < 4; j++) {
            int cc = bn + tcol * 4 + j;
            if (cc >= N) continue;
            size_t off = (size_t)cr * ldc + cc;
            float v = acc[i][j];
            if (EPI == 0) {
                C[off] = v;
            } else {
                v += bias[cc];
                C[off] = (v > 20.f) ? v : log1pf(__expf(v));
            }
        }
    }
}

// ---------------- causal depthwise conv (K=4) + bias + SiLU ----------------
__global__ void conv_silu_kernel(const float* __restrict__ uz, const float* __restrict__ cw,
                                 const float* __restrict__ cb, float* __restrict__ u) {
    int idx = blockIdx.x * blockDim.x + threadIdx.x;
    if (idx >= BLR * EE) return;
    int e = idx % EE;
    int bl = idx / EE;
    int l = bl % LLEN;
    const float* up = uz + (size_t)(bl - l) * (2 * EE) + e;
    float a = cb[e];
#pragma unroll
    for (int k = 0; k < CKW; k++) {
        int lp = l - (CKW - 1) + k;
        if (lp >= 0) a = fmaf(up[(size_t)lp * (2 * EE)], cw[e * CKW + k], a);
    }
    u[idx] = a / (1.f + __expf(-a));
}

// ---------------- selective scan: 2 channels per warp, fused gate ----------
__global__ void scan_kernel(const float* __restrict__ u, const float* __restrict__ delta,
                            const float* __restrict__ uz, const float* __restrict__ dbc,
                            const float* __restrict__ A_log, const float* __restrict__ Dsk,
                            float* __restrict__ y) {
    int w = (blockIdx.x * blockDim.x + threadIdx.x) >> 5;
    int lane = threadIdx.x & 31;
    if (w >= BB * EE / 2) return;
    int b = w / (EE / 2);
    int e = (w - b * (EE / 2)) * 2 + (lane >> 4);
    int s = lane & 15;

    float Ae = -__expf(A_log[e * SSZ + s]);
    float dskip = Dsk[e];
    const float* dptr = delta + (size_t)b * LLEN * EE + e;
    const float* uptr = u + (size_t)b * LLEN * EE + e;
    const float* zptr = uz + (size_t)b * LLEN * 2 * EE + EE + e;
    const float* bc = dbc + (size_t)b * LLEN * 96;
    float* yptr = y + (size_t)b * LLEN * EE + e;

    float hs = 0.f;
    for (int l = 0; l < LLEN; l++) {
        float dlt = dptr[(size_t)l * EE];
        float ul = uptr[(size_t)l * EE];
        float Bv = bc[l * 96 + RRK + s];
        float Cv = bc[l * 96 + RRK + SSZ + s];
        hs = fmaf(__expf(dlt * Ae), hs, (dlt * ul) * Bv);
        float p = hs * Cv;
        p += __shfl_xor_sync(0xffffffffu, p, 8);
        p += __shfl_xor_sync(0xffffffffu, p, 4);
        p += __shfl_xor_sync(0xffffffffu, p, 2);
        p += __shfl_xor_sync(0xffffffffu, p, 1);
        if ((lane & 15) == 0) {
            float z = zptr[(size_t)l * 2 * EE];
            float sz = z / (1.f + __expf(-z));
            yptr[(size_t)l * EE] = (p + ul * dskip) * sz;
        }
    }
}

// ---------------- reward-weight reduction ----------------
__global__ void wmean_kernel(const float* __restrict__ W_rw, const float* __restrict__ b_rw,
                             float* __restrict__ wm) {
    int d = blockIdx.x * blockDim.x + threadIdx.x;
    if (d < DD) {
        float sum = 0.f;
#pragma unroll
        for (int j = 0; j < SSZ; j++) sum += W_rw[d * SSZ + j];
        wm[d] = sum * (1.f / SSZ);
    }
    if (d == 0) {
        float sum = 0.f;
#pragma unroll
        for (int j = 0; j < SSZ; j++) sum += b_rw[j];
        wm[DD] = sum * (1.f / SSZ);
    }
}

// ---------------- per-row scale ----------------
__global__ void rowscale_kernel(float* __restrict__ h, const float* __restrict__ wm) {
    int row = blockIdx.x;
    float4* hr = reinterpret_cast<float4*>(h + (size_t)row * DD);
    float4 hv = hr[threadIdx.x];
    float4 wv = reinterpret_cast<const float4*>(wm)[threadIdx.x];
    float dot = hv.x * wv.x + hv.y * wv.y + hv.z * wv.z + hv.w * wv.w;
    float s = block_reduce_sum(dot) + wm[DD];
    hr[threadIdx.x] = make_float4(hv.x * s, hv.y * s, hv.z * s, hv.w * s);
}

// ---------------- final LayerNorm ----------------
__global__ void ln_kernel(const float* __restrict__ h, const float* __restrict__ g,
                          const float* __restrict__ bta, float* __restrict__ out) {
    int row = blockIdx.x;
    const float4* hr = reinterpret_cast<const float4*>(h + (size_t)row * DD);
    float4 v = hr[threadIdx.x];
    float sm = v.x + v.y + v.z + v.w;
    float sq = v.x * v.x + v.y * v.y + v.z * v.z + v.w * v.w;
    float mu = block_reduce_sum(sm) / (float)DD;
    float var = block_reduce_sum(sq) / (float)DD - mu * mu;
    float inv = rsqrtf(var + 1e-5f);
    float4 gv = reinterpret_cast<const float4*>(g)[threadIdx.x];
    float4 bv = reinterpret_cast<const float4*>(bta)[threadIdx.x];
    float4 o = make_float4((v.x - mu) * inv * gv.x + bv.x,
                           (v.y - mu) * inv * gv.y + bv.y,
                           (v.z - mu) * inv * gv.z + bv.z,
                           (v.w - mu) * inv * gv.w + bv.w);
    reinterpret_cast<float4*>(out + (size_t)row * DD)[threadIdx.x] = o;
}

// ---------------- host orchestration ----------------
extern "C" void kernel_launch(void* const* d_in, const int* in_sizes, int n_in,
                              void* d_out, int out_size) {
    const int* x = (const int*)d_in[0];
    const float* mask = (const float*)d_in[1];
    const float* emb = (const float*)d_in[2];
    const float* norm_w = (const float*)d_in[3];
    const float* W_in = (const float*)d_in[4];
    const float* conv_w = (const float*)d_in[5];
    const float* conv_b = (const float*)d_in[6];
    const float* W_x = (const float*)d_in[7];
    const float* W_dt = (const float*)d_in[8];
    const float* b_dt = (const float*)d_in[9];
    const float* A_log = (const float*)d_in[10];
    const float* D_skip = (const float*)d_in[11];
    const float* W_out = (const float*)d_in[12];
    const float* W_rw = (const float*)d_in[13];
    const float* b_rw = (const float*)d_in[14];
    const float* ln_g = (const float*)d_in[15];
    const float* ln_b = (const float*)d_in[16];
    const float* head_W = (const float*)d_in[17];
    float* out = (float*)d_out;

    float *h_, *xn_, *uz_, *u_, *dbc_, *delta_, *y_, *wm_;
    cudaGetSymbolAddress((void**)&h_, g_h);
    cudaGetSymbolAddress((void**)&xn_, g_xn);
    cudaGetSymbolAddress((void**)&uz_, g_uz);
    cudaGetSymbolAddress((void**)&u_, g_u);
    cudaGetSymbolAddress((void**)&dbc_, g_dbc);
    cudaGetSymbolAddress((void**)&delta_, g_delta);
    cudaGetSymbolAddress((void**)&y_, g_y);
    cudaGetSymbolAddress((void**)&wm_, g_wm);

    embed_kernel<<<BLR, 256>>>(x, mask, emb, h_);

    for (int i = 0; i < NLAY; i++) {
        rmsnorm_kernel<<<BLR, 256>>>(h_, norm_w + (size_t)i * DD, xn_);

        // xn @ W_in -> uz  (2048 x 4096 x 1024)  [tensor core tf32]
        {
            dim3 g((2 * EE) / 128, BLR / 128);
            tf32_gemm<0><<<g, 256>>>(xn_, W_in + (size_t)i * DD * 2 * EE, uz_, 2 * EE, DD);
        }

        conv_silu_kernel<<<(BLR * EE) / 256, 256>>>(uz_, conv_w + (size_t)i * EE * CKW,
                                                    conv_b + (size_t)i * EE, u_);

        // u @ W_x -> dbc  (2048 x 96 x 2048)  [fp32 SIMT, small]
        {
            dim3 g((96 + 63) / 64, BLR / 128);
            gemm_kernel<0><<<g, 256>>>(u_, W_x + (size_t)i * EE * 96, nullptr, dbc_,
                                       BLR, 96, EE, EE, 96, 96);
        }

        // delta = softplus(dr @ W_dt + b_dt)  (2048 x 2048 x 64)  [fp32 SIMT]
        {
            dim3 g((EE + 63) / 64, BLR / 128);
            gemm_kernel<2><<<g, 256>>>(dbc_, W_dt + (size_t)i * RRK * EE,
                                       b_dt + (size_t)i * EE, delta_,
                                       BLR, EE, RRK, 96, EE, EE);
        }

        // selective scan + D skip + SiLU gate -> y
        scan_kernel<<<(BB * EE / 2) * 32 / 256, 256>>>(u_, delta_, uz_, dbc_,
                                                       A_log + (size_t)i * EE * SSZ,
                                                       D_skip + (size_t)i * EE, y_);

        // h += y @ W_out  (2048 x 1024 x 2048)  [tensor core tf32, fused residual]
        {
            dim3 g(DD / 128, BLR / 128);
            tf32_gemm<1><<<g, 256>>>(y_, W_out + (size_t)i * EE * DD, h_, DD, EE);
        }

        // reward-weight scaling: h *= mean_s(h @ W_rw + b_rw)
        wmean_kernel<<<DD / 256, 256>>>(W_rw + (size_t)i * DD * SSZ,
                                        b_rw + (size_t)i * SSZ, wm_);
        rowscale_kernel<<<BLR, 256>>>(h_, wm_);
    }

    ln_kernel<<<BLR, 256>>>(h_, ln_g, ln_b, xn_);

    // logits = xn @ head_W  (2048 x 32000 x 1024)  [tensor core tf32]
    {
        dim3 g(VV / 128, BLR / 128);
        tf32_gemm<0><<<g, 256>>>(xn_, head_W, out, VV, DD);
    }
}

// round 6
// speedup vs baseline: 2.0503x; 1.5583x over previous
#include <cuda_runtime.h>
#include <cuda_fp16.h>
#include <cstdint>

// ---------------- problem constants ----------------
#define BB   2
#define LLEN 1024
#define DD   1024
#define EE   2048
#define SSZ  16
#define RRK  64
#define CKW  4
#define NLAY 4
#define VV   32000
#define BLR  (BB * LLEN)      // 2048 rows

// ---------------- scratch (device globals; no allocation allowed) ----------
__device__ float g_h[BLR * DD];            // residual stream
__device__ float g_uz[BLR * 2 * EE];       // W_in output
__device__ float g_u[BLR * EE];            // post conv+silu
__device__ float g_dbc[BLR * 96];          // dr|B|C
__device__ float g_delta[BLR * EE];        // softplus output
__device__ float g_wm[DD + 1];             // mean-over-S of W_rw, + mean b_rw
// half activations / weights for tensor-core GEMMs
__device__ __half g_xn_h[BLR * DD];        // rmsnorm out / ln out
__device__ __half g_y_h[BLR * EE];         // gated scan output
__device__ __half g_win_h[NLAY * DD * 2 * EE];
__device__ __half g_wout_h[NLAY * EE * DD];
__device__ __half g_head_h[DD * VV];

// ---------------- small helpers ----------------
__device__ __forceinline__ float block_reduce_sum(float v) {
    __shared__ float red[8];
    __shared__ float tot;
    int lane = threadIdx.x & 31, wid = threadIdx.x >> 5;
#pragma unroll
    for (int o = 16; o; o >>= 1) v += __shfl_xor_sync(0xffffffffu, v, o);
    if (lane == 0) red[wid] = v;
    __syncthreads();
    if (wid == 0) {
        float w = (threadIdx.x < (blockDim.x >> 5)) ? red[threadIdx.x] : 0.f;
#pragma unroll
        for (int o = 4; o; o >>= 1) w += __shfl_xor_sync(0xffffffffu, w, o);
        if (threadIdx.x == 0) tot = w;
    }
    __syncthreads();
    return tot;
}

__device__ __forceinline__ uint32_t smem_u32(const void* p) {
    uint32_t a;
    asm("{ .reg .u64 t; cvta.to.shared.u64 t, %1; cvt.u32.u64 %0, t; }" : "=r"(a) : "l"(p));
    return a;
}
__device__ __forceinline__ void cp16(uint32_t dst, const void* src) {
    asm volatile("cp.async.cg.shared.global [%0], [%1], 16;" :: "r"(dst), "l"(src) : "memory");
}
__device__ __forceinline__ void cp_commit() { asm volatile("cp.async.commit_group;" ::: "memory"); }
template <int N>
__device__ __forceinline__ void cp_wait() { asm volatile("cp.async.wait_group %0;" :: "n"(N) : "memory"); }

__device__ __forceinline__ void ldsm_x4(uint32_t* r, uint32_t addr) {
    asm volatile("ldmatrix.sync.aligned.m8n8.x4.shared.b16 {%0,%1,%2,%3}, [%4];"
                 : "=r"(r[0]), "=r"(r[1]), "=r"(r[2]), "=r"(r[3]) : "r"(addr));
}
__device__ __forceinline__ void ldsm_x4t(uint32_t* r, uint32_t addr) {
    asm volatile("ldmatrix.sync.aligned.m8n8.x4.trans.shared.b16 {%0,%1,%2,%3}, [%4];"
                 : "=r"(r[0]), "=r"(r[1]), "=r"(r[2]), "=r"(r[3]) : "r"(addr));
}
__device__ __forceinline__ void mma_f16(float* c, const uint32_t* a, const uint32_t* b) {
    asm volatile(
        "mma.sync.aligned.m16n8k16.row.col.f32.f16.f16.f32 "
        "{%0,%1,%2,%3}, {%4,%5,%6,%7}, {%8,%9}, {%0,%1,%2,%3};"
        : "+f"(c[0]), "+f"(c[1]), "+f"(c[2]), "+f"(c[3])
        : "r"(a[0]), "r"(a[1]), "r"(a[2]), "r"(a[3]), "r"(b[0]), "r"(b[1]));
}

// ================= fp16 tensor-core GEMM (mma.sync + ldmatrix + cp.async) ====
// C[2048, N] (f32) = A[2048, K] (f16) @ B[K, N] (f16).
// Requires M%128==0, N%128==0, K%32==0.  EPI: 0 = store, 1 = C += result.
// CTA 128x128x32, 256 threads, 8 warps (2m x 4n), warp tile 64x32.
// smem per stage: A 128 rows x 80B (64B data, pad->conflict-free ldmatrix) = 10240B
//                 B 32 rows x 256B (XOR-swizzled 16B chunks)               =  8192B
#define HNST 4
#define HSTG 18432
#define HG_SMEM (HNST * HSTG)     // 73728 B

template <int EPI>
__global__ void __launch_bounds__(256, 2)
hgemm(const __half* __restrict__ A, const __half* __restrict__ B,
      float* __restrict__ C, int N, int K) {
    extern __shared__ char smem[];
    const uint32_t sb = smem_u32(smem);
    const int tid = threadIdx.x, wid = tid >> 5, lane = tid & 31;
    const int bm = blockIdx.x * 128, bn = blockIdx.y * 128;
    const int wm = (wid >> 2) * 64, wn = (wid & 3) * 32;
    const int nk = K / 32;

    // producer: 2 A-chunks + 2 B-chunks (16B each) per thread per stage
    const int pa_row = tid >> 1;                 // A: idx = tid*2+i -> row=idx>>2
    auto issue_stage = [&](int kb) {
        uint32_t stg = sb + (kb % HNST) * HSTG;
        const __half* As = A + (size_t)bm * K + kb * 32;
        const __half* Bsrc = B + (size_t)kb * 32 * N + bn;
#pragma unroll
        for (int i = 0; i < 2; i++) {
            int idx = tid * 2 + i;
            int r = idx >> 2, c = idx & 3;
            cp16(stg + r * 80 + c * 16, As + (size_t)r * K + c * 8);
        }
#pragma unroll
        for (int i = 0; i < 2; i++) {
            int idx = tid * 2 + i;
            int k = idx >> 4, c = idx & 15;
            cp16(stg + 10240 + k * 256 + ((c ^ (k & 7)) << 4),
                 Bsrc + (size_t)k * N + c * 8);
        }
        cp_commit();
    };

    float acc[4][4][4];
#pragma unroll
    for (int mt = 0; mt < 4; mt++)
#pragma unroll
        for (int nt = 0; nt < 4; nt++)
#pragma unroll
            for (int q = 0; q < 4; q++) acc[mt][nt][q] = 0.f;

    // consumer per-lane address pieces
    const uint32_t a_off = (uint32_t)((lane & 15) * 80 + (lane >> 4) * 16);
    const int kl = (lane & 7) + ((lane >> 3) & 1) * 8;         // B k-row within 16
    const int nsel = (lane >> 4) * 8;                          // +8 cols for hi half

    issue_stage(0); issue_stage(1); issue_stage(2);

    for (int kb = 0; kb < nk; kb++) {
        if (kb + 3 < nk) { issue_stage(kb + 3); cp_wait<3>(); }
        else             { cp_wait<0>(); }
        __syncthreads();

        uint32_t Ab = sb + (kb % HNST) * HSTG;
        uint32_t Bb = Ab + 10240;
#pragma unroll
        for (int ks = 0; ks < 2; ks++) {
            uint32_t af[4][4], bf[2][4];
#pragma unroll
            for (int mt = 0; mt < 4; mt++)
                ldsm_x4(af[mt], Ab + (uint32_t)((wm + mt * 16) * 80) + a_off + ks * 32);
#pragma unroll
            for (int p = 0; p < 2; p++) {
                int n0 = wn + p * 16 + nsel;
                uint32_t nch = (uint32_t)((n0 >> 3) ^ (kl & 7));
                ldsm_x4t(bf[p], Bb + (uint32_t)((ks * 16 + kl) * 256) + (nch << 4));
            }
#pragma unroll
            for (int mt = 0; mt < 4; mt++)
#pragma unroll
                for (int nt = 0; nt < 4; nt++)
                    mma_f16(acc[mt][nt], af[mt], &bf[nt >> 1][(nt & 1) * 2]);
        }
        __syncthreads();
    }

    // epilogue: direct coalesced-ish stores (float2 per fragment row)
    const int gid = lane >> 2, tig = lane & 3;
#pragma unroll
    for (int mt = 0; mt < 4; mt++) {
        int row = bm + wm + mt * 16 + gid;
#pragma unroll
        for (int nt = 0; nt < 4; nt++) {
            int col = bn + wn + nt * 8 + tig * 2;
            float2* c0 = reinterpret_cast<float2*>(C + (size_t)row * N + col);
            float2* c1 = reinterpret_cast<float2*>(C + (size_t)(row + 8) * N + col);
            float2 v0 = make_float2(acc[mt][nt][0], acc[mt][nt][1]);
            float2 v1 = make_float2(acc[mt][nt][2], acc[mt][nt][3]);
            if (EPI == 1) {
                float2 o0 = *c0, o1 = *c1;
                v0.x += o0.x; v0.y += o0.y; v1.x += o1.x; v1.y += o1.y;
            }
            *c0 = v0; *c1 = v1;
        }
    }
}

// ---------------- fp32 -> fp16 conversion (weights) ----------------
__global__ void f2h_kernel(const float* __restrict__ in, __half* __restrict__ out, int n4) {
    int i = blockIdx.x * blockDim.x + threadIdx.x;
    if (i >= n4) return;
    float4 v = reinterpret_cast<const float4*>(in)[i];
    __half2 h0 = __floats2half2_rn(v.x, v.y);
    __half2 h1 = __floats2half2_rn(v.z, v.w);
    reinterpret_cast<__half2*>(out)[2 * i] = h0;
    reinterpret_cast<__half2*>(out)[2 * i + 1] = h1;
}

// ---------------- embedding ----------------
__global__ void embed_kernel(const int* __restrict__ x, const float* __restrict__ mask,
                             const float* __restrict__ emb, float* __restrict__ h) {
    int row = blockIdx.x;
    int tok = x[row];
    float m = mask[row];
    const float4* src = reinterpret_cast<const float4*>(emb + (size_t)tok * DD);
    float4* dst = reinterpret_cast<float4*>(h + (size_t)row * DD);
    float4 v = src[threadIdx.x];
    dst[threadIdx.x] = make_float4(v.x * m, v.y * m, v.z * m, v.w * m);
}

// ---------------- RMSNorm (half output) ----------------
__global__ void rmsnorm_kernel(const float* __restrict__ x, const float* __restrict__ w,
                               __half* __restrict__ out) {
    int row = blockIdx.x;
    const float4* xr = reinterpret_cast<const float4*>(x + (size_t)row * DD);
    float4 v = xr[threadIdx.x];
    float ss = v.x * v.x + v.y * v.y + v.z * v.z + v.w * v.w;
    float tot = block_reduce_sum(ss);
    float scale = rsqrtf(tot / (float)DD + 1e-5f);
    float4 wv = reinterpret_cast<const float4*>(w)[threadIdx.x];
    __half2 h0 = __floats2half2_rn(v.x * scale * wv.x, v.y * scale * wv.y);
    __half2 h1 = __floats2half2_rn(v.z * scale * wv.z, v.w * scale * wv.w);
    __half2* o = reinterpret_cast<__half2*>(out + (size_t)row * DD);
    o[2 * threadIdx.x] = h0;
    o[2 * threadIdx.x + 1] = h1;
}

// ---------------- generic fp32 SIMT GEMM (small shapes) ----------------
// EPI: 0 = store, 2 = softplus(v + bias[col])
template <int EPI>
__global__ void __launch_bounds__(256)
gemm_kernel(const float* __restrict__ A, const float* __restrict__ B,
            const float* __restrict__ bias, float* __restrict__ C,
            int M, int N, int Kd, int lda, int ldb, int ldc) {
    constexpr int BM = 128, BN = 64, BK = 16;
    __shared__ float As[BK][BM + 4];
    __shared__ float Bs[BK][BN];
    int tid = threadIdx.x;
    int bm = blockIdx.y * BM;
    int bn = blockIdx.x * BN;
    int trow = tid >> 4;
    int tcol = tid & 15;

    float acc[8][4];
#pragma unroll
    for (int i = 0; i < 8; i++)
#pragma unroll
        for (int j = 0; j < 4; j++) acc[i][j] = 0.f;

    for (int k0 = 0; k0 < Kd; k0 += BK) {
#pragma unroll
        for (int i = 0; i < 2; i++) {
            int idx = tid * 2 + i;
            int r = idx >> 2, kq = idx & 3;
            float4 v = make_float4(0.f, 0.f, 0.f, 0.f);
            int arow = bm + r;
            if (arow < M)
                v = *reinterpret_cast<const float4*>(A + (size_t)arow * lda + k0 + kq * 4);
            As[kq * 4 + 0][r] = v.x;
            As[kq * 4 + 1][r] = v.y;
            As[kq * 4 + 2][r] = v.z;
            As[kq * 4 + 3][r] = v.w;
        }
        {
            int krow = tid >> 4, nq = tid & 15;
            float4 v = make_float4(0.f, 0.f, 0.f, 0.f);
            int bcol = bn + nq * 4;
            if (bcol < N)
                v = *reinterpret_cast<const float4*>(B + (size_t)(k0 + krow) * ldb + bcol);
            *reinterpret_cast<float4*>(&Bs[krow][nq * 4]) = v;
        }
        __syncthreads();
#pragma unroll
        for (int kk = 0; kk < BK; kk++) {
            float4 a0 = *reinterpret_cast<const float4*>(&As[kk][trow * 8]);
            float4 a1 = *reinterpret_cast<const float4*>(&As[kk][trow * 8 + 4]);
            float4 b0 = *reinterpret_cast<const float4*>(&Bs[kk][tcol * 4]);
            float ar[8] = {a0.x, a0.y, a0.z, a0.w, a1.x, a1.y, a1.z, a1.w};
            float br[4] = {b0.x, b0.y, b0.z, b0.w};
#pragma unroll
            for (int i = 0; i < 8; i++)
#pragma unroll
                for (int j = 0; j < 4; j++)
                    acc[i][j] = fmaf(ar[i], br[j], acc[i][j]);
        }
        __syncthreads();
    }

#pragma unroll
    for (int i = 0; i < 8; i++) {
        int cr = bm + trow * 8 + i;
        if (cr >= M) continue;
#pragma unroll
        for (int j = 0; j < 4; j++) {
            int cc = bn + tcol * 4 + j;
            if (cc >= N) continue;
            size_t off = (size_t)cr * ldc + cc;
            float v = acc[i][j];
            if (EPI == 0) {
                C[off] = v;
            } else {
                v += bias[cc];
                C[off] = (v > 20.f) ? v : log1pf(__expf(v));
            }
        }
    }
}

// ---------------- causal depthwise conv (K=4) + bias + SiLU ----------------
__global__ void conv_silu_kernel(const float* __restrict__ uz, const float* __restrict__ cw,
                                 const float* __restrict__ cb, float* __restrict__ u) {
    int idx = blockIdx.x * blockDim.x + threadIdx.x;
    if (idx >= BLR * EE) return;
    int e = idx % EE;
    int bl = idx / EE;
    int l = bl % LLEN;
    const float* up = uz + (size_t)(bl - l) * (2 * EE) + e;
    float a = cb[e];
#pragma unroll
    for (int k = 0; k < CKW; k++) {
        int lp = l - (CKW - 1) + k;
        if (lp >= 0) a = fmaf(up[(size_t)lp * (2 * EE)], cw[e * CKW + k], a);
    }
    u[idx] = a / (1.f + __expf(-a));
}

// ---------------- selective scan (half y output) ----------------
__global__ void scan_kernel(const float* __restrict__ u, const float* __restrict__ delta,
                            const float* __restrict__ uz, const float* __restrict__ dbc,
                            const float* __restrict__ A_log, const float* __restrict__ Dsk,
                            __half* __restrict__ y) {
    int w = (blockIdx.x * blockDim.x + threadIdx.x) >> 5;
    int lane = threadIdx.x & 31;
    if (w >= BB * EE / 2) return;
    int b = w / (EE / 2);
    int e = (w - b * (EE / 2)) * 2 + (lane >> 4);
    int s = lane & 15;

    float Ae = -__expf(A_log[e * SSZ + s]);
    float dskip = Dsk[e];
    const float* dptr = delta + (size_t)b * LLEN * EE + e;
    const float* uptr = u + (size_t)b * LLEN * EE + e;
    const float* zptr = uz + (size_t)b * LLEN * 2 * EE + EE + e;
    const float* bc = dbc + (size_t)b * LLEN * 96;
    __half* yptr = y + (size_t)b * LLEN * EE + e;

    float hs = 0.f;
    for (int l = 0; l < LLEN; l++) {
        float dlt = dptr[(size_t)l * EE];
        float ul = uptr[(size_t)l * EE];
        float Bv = bc[l * 96 + RRK + s];
        float Cv = bc[l * 96 + RRK + SSZ + s];
        hs = fmaf(__expf(dlt * Ae), hs, (dlt * ul) * Bv);
        float p = hs * Cv;
        p += __shfl_xor_sync(0xffffffffu, p, 8);
        p += __shfl_xor_sync(0xffffffffu, p, 4);
        p += __shfl_xor_sync(0xffffffffu, p, 2);
        p += __shfl_xor_sync(0xffffffffu, p, 1);
        if ((lane & 15) == 0) {
            float z = zptr[(size_t)l * 2 * EE];
            float sz = z / (1.f + __expf(-z));
            yptr[(size_t)l * EE] = __float2half_rn((p + ul * dskip) * sz);
        }
    }
}

// ---------------- reward-weight reduction ----------------
__global__ void wmean_kernel(const float* __restrict__ W_rw, const float* __restrict__ b_rw,
                             float* __restrict__ wm) {
    int d = blockIdx.x * blockDim.x + threadIdx.x;
    if (d < DD) {
        float sum = 0.f;
#pragma unroll
        for (int j = 0; j < SSZ; j++) sum += W_rw[d * SSZ + j];
        wm[d] = sum * (1.f / SSZ);
    }
    if (d == 0) {
        float sum = 0.f;
#pragma unroll
        for (int j = 0; j < SSZ; j++) sum += b_rw[j];
        wm[DD] = sum * (1.f / SSZ);
    }
}

// ---------------- per-row scale ----------------
__global__ void rowscale_kernel(float* __restrict__ h, const float* __restrict__ wm) {
    int row = blockIdx.x;
    float4* hr = reinterpret_cast<float4*>(h + (size_t)row * DD);
    float4 hv = hr[threadIdx.x];
    float4 wv = reinterpret_cast<const float4*>(wm)[threadIdx.x];
    float dot = hv.x * wv.x + hv.y * wv.y + hv.z * wv.z + hv.w * wv.w;
    float s = block_reduce_sum(dot) + wm[DD];
    hr[threadIdx.x] = make_float4(hv.x * s, hv.y * s, hv.z * s, hv.w * s);
}

// ---------------- final LayerNorm (half output) ----------------
__global__ void ln_kernel(const float* __restrict__ h, const float* __restrict__ g,
                          const float* __restrict__ bta, __half* __restrict__ out) {
    int row = blockIdx.x;
    const float4* hr = reinterpret_cast<const float4*>(h + (size_t)row * DD);
    float4 v = hr[threadIdx.x];
    float sm = v.x + v.y + v.z + v.w;
    float sq = v.x * v.x + v.y * v.y + v.z * v.z + v.w * v.w;
    float mu = block_reduce_sum(sm) / (float)DD;
    float var = block_reduce_sum(sq) / (float)DD - mu * mu;
    float inv = rsqrtf(var + 1e-5f);
    float4 gv = reinterpret_cast<const float4*>(g)[threadIdx.x];
    float4 bv = reinterpret_cast<const float4*>(bta)[threadIdx.x];
    __half2 h0 = __floats2half2_rn((v.x - mu) * inv * gv.x + bv.x,
                                   (v.y - mu) * inv * gv.y + bv.y);
    __half2 h1 = __floats2half2_rn((v.z - mu) * inv * gv.z + bv.z,
                                   (v.w - mu) * inv * gv.w + bv.w);
    __half2* o = reinterpret_cast<__half2*>(out + (size_t)row * DD);
    o[2 * threadIdx.x] = h0;
    o[2 * threadIdx.x + 1] = h1;
}

// ---------------- host orchestration ----------------
extern "C" void kernel_launch(void* const* d_in, const int* in_sizes, int n_in,
                              void* d_out, int out_size) {
    const int* x = (const int*)d_in[0];
    const float* mask = (const float*)d_in[1];
    const float* emb = (const float*)d_in[2];
    const float* norm_w = (const float*)d_in[3];
    const float* W_in = (const float*)d_in[4];
    const float* conv_w = (const float*)d_in[5];
    const float* conv_b = (const float*)d_in[6];
    const float* W_x = (const float*)d_in[7];
    const float* W_dt = (const float*)d_in[8];
    const float* b_dt = (const float*)d_in[9];
    const float* A_log = (const float*)d_in[10];
    const float* D_skip = (const float*)d_in[11];
    const float* W_out = (const float*)d_in[12];
    const float* W_rw = (const float*)d_in[13];
    const float* b_rw = (const float*)d_in[14];
    const float* ln_g = (const float*)d_in[15];
    const float* ln_b = (const float*)d_in[16];
    const float* head_W = (const float*)d_in[17];
    float* out = (float*)d_out;

    float *h_, *uz_, *u_, *dbc_, *delta_, *wm_;
    __half *xnh_, *yh_, *winh_, *wouth_, *headh_;
    cudaGetSymbolAddress((void**)&h_, g_h);
    cudaGetSymbolAddress((void**)&uz_, g_uz);
    cudaGetSymbolAddress((void**)&u_, g_u);
    cudaGetSymbolAddress((void**)&dbc_, g_dbc);
    cudaGetSymbolAddress((void**)&delta_, g_delta);
    cudaGetSymbolAddress((void**)&wm_, g_wm);
    cudaGetSymbolAddress((void**)&xnh_, g_xn_h);
    cudaGetSymbolAddress((void**)&yh_, g_y_h);
    cudaGetSymbolAddress((void**)&winh_, g_win_h);
    cudaGetSymbolAddress((void**)&wouth_, g_wout_h);
    cudaGetSymbolAddress((void**)&headh_, g_head_h);

    cudaFuncSetAttribute(hgemm<0>, cudaFuncAttributeMaxDynamicSharedMemorySize, HG_SMEM);
    cudaFuncSetAttribute(hgemm<1>, cudaFuncAttributeMaxDynamicSharedMemorySize, HG_SMEM);

    // convert weights to fp16 scratch
    {
        int n4 = NLAY * DD * 2 * EE / 4;
        f2h_kernel<<<(n4 + 255) / 256, 256>>>(W_in, winh_, n4);
        n4 = NLAY * EE * DD / 4;
        f2h_kernel<<<(n4 + 255) / 256, 256>>>(W_out, wouth_, n4);
        n4 = DD * VV / 4;
        f2h_kernel<<<(n4 + 255) / 256, 256>>>(head_W, headh_, n4);
    }

    embed_kernel<<<BLR, 256>>>(x, mask, emb, h_);

    for (int i = 0; i < NLAY; i++) {
        rmsnorm_kernel<<<BLR, 256>>>(h_, norm_w + (size_t)i * DD, xnh_);

        // uz = xn @ W_in   (2048 x 4096 x 1024)  [fp16 mma.sync]
        {
            dim3 g(BLR / 128, (2 * EE) / 128);
            hgemm<0><<<g, 256, HG_SMEM>>>(xnh_, winh_ + (size_t)i * DD * 2 * EE,
                                          uz_, 2 * EE, DD);
        }

        conv_silu_kernel<<<(BLR * EE) / 256, 256>>>(uz_, conv_w + (size_t)i * EE * CKW,
                                                    conv_b + (size_t)i * EE, u_);

        // dbc = u @ W_x    (2048 x 96 x 2048)  [fp32 SIMT]
        {
            dim3 g((96 + 63) / 64, BLR / 128);
            gemm_kernel<0><<<g, 256>>>(u_, W_x + (size_t)i * EE * 96, nullptr, dbc_,
                                       BLR, 96, EE, EE, 96, 96);
        }

        // delta = softplus(dr @ W_dt + b_dt)  (2048 x 2048 x 64)  [fp32 SIMT]
        {
            dim3 g((EE + 63) / 64, BLR / 128);
            gemm_kernel<2><<<g, 256>>>(dbc_, W_dt + (size_t)i * RRK * EE,
                                       b_dt + (size_t)i * EE, delta_,
                                       BLR, EE, RRK, 96, EE, EE);
        }

        // selective scan + D skip + SiLU gate -> y (fp16)
        scan_kernel<<<(BB * EE / 2) * 32 / 256, 256>>>(u_, delta_, uz_, dbc_,
                                                       A_log + (size_t)i * EE * SSZ,
                                                       D_skip + (size_t)i * EE, yh_);

        // h += y @ W_out   (2048 x 1024 x 2048)  [fp16 mma.sync, fused residual]
        {
            dim3 g(BLR / 128, DD / 128);
            hgemm<1><<<g, 256, HG_SMEM>>>(yh_, wouth_ + (size_t)i * EE * DD, h_, DD, EE);
        }

        // reward-weight scaling
        wmean_kernel<<<DD / 256, 256>>>(W_rw + (size_t)i * DD * SSZ,
                                        b_rw + (size_t)i * SSZ, wm_);
        rowscale_kernel<<<BLR, 256>>>(h_, wm_);
    }

    ln_kernel<<<BLR, 256>>>(h_, ln_g, ln_b, xnh_);

    // logits = xn @ head_W  (2048 x 32000 x 1024)  [fp16 mma.sync]
    {
        dim3 g(BLR / 128, VV / 128);
        hgemm<0><<<g, 256, HG_SMEM>>>(xnh_, headh_, out, VV, DD);
    }
}

// round 7
// speedup vs baseline: 2.1970x; 1.0715x over previous
#include <cuda_runtime.h>
#include <cuda_fp16.h>
#include <cstdint>

// ---------------- problem constants ----------------
#define BB   2
#define LLEN 1024
#define DD   1024
#define EE   2048
#define SSZ  16
#define RRK  64
#define CKW  4
#define NLAY 4
#define VV   32000
#define BLR  (BB * LLEN)      // 2048 rows
#define KSPL 8                // split-K factor for W_x GEMM

// ---------------- scratch (device globals; no allocation allowed) ----------
__device__ float g_h[BLR * DD];            // residual stream
__device__ float g_uz[BLR * 2 * EE];       // W_in output
__device__ float g_u[BLR * EE];            // post conv+silu
__device__ float g_dbc[BLR * 96];          // dr|B|C
__device__ float g_dbc_part[KSPL * BLR * 96];  // split-K partials
__device__ float g_delta[BLR * EE];        // softplus output
__device__ float g_wm[DD + 1];             // mean-over-S of W_rw, + mean b_rw
// half activations / weights for tensor-core GEMMs
__device__ __half g_xn_h[BLR * DD];        // rmsnorm out / ln out
__device__ __half g_y_h[BLR * EE];         // gated scan output
__device__ __half g_win_h[NLAY * DD * 2 * EE];
__device__ __half g_wout_h[NLAY * EE * DD];
__device__ __half g_head_h[DD * VV];

// ---------------- small helpers ----------------
__device__ __forceinline__ float block_reduce_sum(float v) {
    __shared__ float red[8];
    __shared__ float tot;
    int lane = threadIdx.x & 31, wid = threadIdx.x >> 5;
#pragma unroll
    for (int o = 16; o; o >>= 1) v += __shfl_xor_sync(0xffffffffu, v, o);
    if (lane == 0) red[wid] = v;
    __syncthreads();
    if (wid == 0) {
        float w = (threadIdx.x < (blockDim.x >> 5)) ? red[threadIdx.x] : 0.f;
#pragma unroll
        for (int o = 4; o; o >>= 1) w += __shfl_xor_sync(0xffffffffu, w, o);
        if (threadIdx.x == 0) tot = w;
    }
    __syncthreads();
    return tot;
}

__device__ __forceinline__ uint32_t smem_u32(const void* p) {
    uint32_t a;
    asm("{ .reg .u64 t; cvta.to.shared.u64 t, %1; cvt.u32.u64 %0, t; }" : "=r"(a) : "l"(p));
    return a;
}
__device__ __forceinline__ void cp16(uint32_t dst, const void* src) {
    asm volatile("cp.async.cg.shared.global [%0], [%1], 16;" :: "r"(dst), "l"(src) : "memory");
}
__device__ __forceinline__ void cp_commit() { asm volatile("cp.async.commit_group;" ::: "memory"); }
template <int N>
__device__ __forceinline__ void cp_wait() { asm volatile("cp.async.wait_group %0;" :: "n"(N) : "memory"); }

__device__ __forceinline__ void ldsm_x4(uint32_t* r, uint32_t addr) {
    asm volatile("ldmatrix.sync.aligned.m8n8.x4.shared.b16 {%0,%1,%2,%3}, [%4];"
                 : "=r"(r[0]), "=r"(r[1]), "=r"(r[2]), "=r"(r[3]) : "r"(addr));
}
__device__ __forceinline__ void ldsm_x4t(uint32_t* r, uint32_t addr) {
    asm volatile("ldmatrix.sync.aligned.m8n8.x4.trans.shared.b16 {%0,%1,%2,%3}, [%4];"
                 : "=r"(r[0]), "=r"(r[1]), "=r"(r[2]), "=r"(r[3]) : "r"(addr));
}
__device__ __forceinline__ void mma_f16(float* c, const uint32_t* a, const uint32_t* b) {
    asm volatile(
        "mma.sync.aligned.m16n8k16.row.col.f32.f16.f16.f32 "
        "{%0,%1,%2,%3}, {%4,%5,%6,%7}, {%8,%9}, {%0,%1,%2,%3};"
        : "+f"(c[0]), "+f"(c[1]), "+f"(c[2]), "+f"(c[3])
        : "r"(a[0]), "r"(a[1]), "r"(a[2]), "r"(a[3]), "r"(b[0]), "r"(b[1]));
}

// ================= fp16 tensor-core GEMM (mma.sync + ldmatrix + cp.async) ====
// C[2048, N] (f32) = A[2048, K] (f16) @ B[K, N] (f16).
// M%128==0, N%BN==0, K%32==0.  BN in {64,128}.  EPI: 0 = store, 1 = C +=.
// CTA 128xBNx32, 256 threads, 8 warps (2m x 4n), warp tile 64 x BN/4.
#define HNST 4

template <int BN, int EPI>
__global__ void __launch_bounds__(256, 2)
hgemm(const __half* __restrict__ A, const __half* __restrict__ B,
      float* __restrict__ C, int N, int K) {
    constexpr int ASTG = 128 * 80;            // A: 128 rows x 80B (64B data + pad)
    constexpr int BROW = BN * 2;              // B row bytes
    constexpr int CH = BN / 8;                // 16B chunks per B row
    constexpr int BSTG = 32 * BROW;
    constexpr int STG = ASTG + BSTG;
    constexpr int NT = BN / 32;               // 8-col mma tiles per warp

    extern __shared__ char smem[];
    const uint32_t sb = smem_u32(smem);
    const int tid = threadIdx.x, wid = tid >> 5, lane = tid & 31;
    const int bm = blockIdx.x * 128, bn = blockIdx.y * BN;
    const int wm = (wid >> 2) * 64, wn = (wid & 3) * (BN / 4);
    const int nk = K / 32;

    auto issue_stage = [&](int kb) {
        uint32_t stg = sb + (kb % HNST) * STG;
        const __half* As = A + (size_t)bm * K + kb * 32;
        const __half* Bsrc = B + (size_t)kb * 32 * N + bn;
#pragma unroll
        for (int i = 0; i < 2; i++) {
            int idx = tid * 2 + i;
            int r = idx >> 2, c = idx & 3;
            cp16(stg + r * 80 + c * 16, As + (size_t)r * K + c * 8);
        }
        constexpr int BPER = (32 * CH) / 256;   // 2 (BN=128) or 1 (BN=64)
#pragma unroll
        for (int i = 0; i < BPER; i++) {
            int idx = tid * BPER + i;
            int k = idx / CH, c = idx % CH;
            cp16(stg + ASTG + k * BROW + ((c ^ (k & 7)) << 4),
                 Bsrc + (size_t)k * N + c * 8);
        }
        cp_commit();
    };

    float acc[4][NT][4];
#pragma unroll
    for (int mt = 0; mt < 4; mt++)
#pragma unroll
        for (int nt = 0; nt < NT; nt++)
#pragma unroll
            for (int q = 0; q < 4; q++) acc[mt][nt][q] = 0.f;

    const uint32_t a_off = (uint32_t)((lane & 15) * 80 + (lane >> 4) * 16);
    const int kl = (lane & 7) + ((lane >> 3) & 1) * 8;   // B k-row within 16
    const int nsel = (lane >> 4) * 8;                    // +8 cols for hi half

    issue_stage(0); issue_stage(1); issue_stage(2);

    for (int kb = 0; kb < nk; kb++) {
        if (kb < nk - 2)      cp_wait<2>();
        else if (kb == nk - 2) cp_wait<1>();
        else                   cp_wait<0>();
        __syncthreads();
        if (kb + 3 < nk) issue_stage(kb + 3);   // overwrites stage (kb-1)%4 — safe post-sync

        uint32_t Ab = sb + (kb % HNST) * STG;
        uint32_t Bb = Ab + ASTG;
#pragma unroll
        for (int ks = 0; ks < 2; ks++) {
            uint32_t af[4][4], bf[NT * 2];
#pragma unroll
            for (int mt = 0; mt < 4; mt++)
                ldsm_x4(af[mt], Ab + (uint32_t)((wm + mt * 16) * 80) + a_off + ks * 32);
#pragma unroll
            for (int p = 0; p < NT / 2; p++) {
                int n0 = wn + p * 16 + nsel;
                uint32_t nch = (uint32_t)((n0 >> 3) ^ (kl & 7));
                ldsm_x4t(&bf[p * 4], Bb + (uint32_t)((ks * 16 + kl) * BROW) + (nch << 4));
            }
#pragma unroll
            for (int mt = 0; mt < 4; mt++)
#pragma unroll
                for (int nt = 0; nt < NT; nt++)
                    mma_f16(acc[mt][nt], af[mt], &bf[nt * 2]);
        }
    }

    const int gid = lane >> 2, tig = lane & 3;
#pragma unroll
    for (int mt = 0; mt < 4; mt++) {
        int row = bm + wm + mt * 16 + gid;
#pragma unroll
        for (int nt = 0; nt < NT; nt++) {
            int col = bn + wn + nt * 8 + tig * 2;
            float2* c0 = reinterpret_cast<float2*>(C + (size_t)row * N + col);
            float2* c1 = reinterpret_cast<float2*>(C + (size_t)(row + 8) * N + col);
            float2 v0 = make_float2(acc[mt][nt][0], acc[mt][nt][1]);
            float2 v1 = make_float2(acc[mt][nt][2], acc[mt][nt][3]);
            if (EPI == 1) {
                float2 o0 = *c0, o1 = *c1;
                v0.x += o0.x; v0.y += o0.y; v1.x += o1.x; v1.y += o1.y;
            }
            *c0 = v0; *c1 = v1;
        }
    }
}

#define HG_SMEM_128 (HNST * (128 * 80 + 32 * 256))   // 73728
#define HG_SMEM_64  (HNST * (128 * 80 + 32 * 128))   // 57344

// ---------------- fp32 -> fp16 conversion (weights) ----------------
__global__ void f2h_kernel(const float* __restrict__ in, __half* __restrict__ out, int n4) {
    int i = blockIdx.x * blockDim.x + threadIdx.x;
    if (i >= n4) return;
    float4 v = reinterpret_cast<const float4*>(in)[i];
    reinterpret_cast<__half2*>(out)[2 * i] = __floats2half2_rn(v.x, v.y);
    reinterpret_cast<__half2*>(out)[2 * i + 1] = __floats2half2_rn(v.z, v.w);
}

// ---------------- embedding ----------------
__global__ void embed_kernel(const int* __restrict__ x, const float* __restrict__ mask,
                             const float* __restrict__ emb, float* __restrict__ h) {
    int row = blockIdx.x;
    int tok = x[row];
    float m = mask[row];
    const float4* src = reinterpret_cast<const float4*>(emb + (size_t)tok * DD);
    float4* dst = reinterpret_cast<float4*>(h + (size_t)row * DD);
    float4 v = src[threadIdx.x];
    dst[threadIdx.x] = make_float4(v.x * m, v.y * m, v.z * m, v.w * m);
}

// ---------------- RMSNorm (half output) ----------------
__global__ void rmsnorm_kernel(const float* __restrict__ x, const float* __restrict__ w,
                               __half* __restrict__ out) {
    int row = blockIdx.x;
    const float4* xr = reinterpret_cast<const float4*>(x + (size_t)row * DD);
    float4 v = xr[threadIdx.x];
    float ss = v.x * v.x + v.y * v.y + v.z * v.z + v.w * v.w;
    float tot = block_reduce_sum(ss);
    float scale = rsqrtf(tot / (float)DD + 1e-5f);
    float4 wv = reinterpret_cast<const float4*>(w)[threadIdx.x];
    __half2* o = reinterpret_cast<__half2*>(out + (size_t)row * DD);
    o[2 * threadIdx.x] = __floats2half2_rn(v.x * scale * wv.x, v.y * scale * wv.y);
    o[2 * threadIdx.x + 1] = __floats2half2_rn(v.z * scale * wv.z, v.w * scale * wv.w);
}

// ---------------- W_x split-K GEMM: part[kc] = u_chunk @ W_x_chunk ----------
// A[BLR, EE] fp32, B[EE, 96] fp32. grid (16 m-tiles, KSPL k-chunks), 256 thr.
__global__ void __launch_bounds__(256)
wx_splitk_kernel(const float* __restrict__ A, const float* __restrict__ B,
                 float* __restrict__ part) {
    __shared__ float As[16][132];
    __shared__ float Bs[16][96];
    const int tid = threadIdx.x;
    const int bm = blockIdx.x * 128;
    const int kc = blockIdx.y * (EE / KSPL);
    const int trow = tid >> 4, tcol = tid & 15;

    float acc[8][6];
#pragma unroll
    for (int i = 0; i < 8; i++)
#pragma unroll
        for (int j = 0; j < 6; j++) acc[i][j] = 0.f;

    for (int k0 = 0; k0 < EE / KSPL; k0 += 16) {
#pragma unroll
        for (int i = 0; i < 2; i++) {
            int idx = tid * 2 + i;
            int r = idx >> 2, kq = idx & 3;
            float4 v = *reinterpret_cast<const float4*>(
                A + (size_t)(bm + r) * EE + kc + k0 + kq * 4);
            As[kq * 4 + 0][r] = v.x;
            As[kq * 4 + 1][r] = v.y;
            As[kq * 4 + 2][r] = v.z;
            As[kq * 4 + 3][r] = v.w;
        }
#pragma unroll
        for (int i = 0; i < 3; i++) {
            int idx = tid + i * 256;
            int r = idx / 48, c = idx % 48;
            float2 v = *reinterpret_cast<const float2*>(B + (size_t)(kc + k0 + r) * 96 + c * 2);
            Bs[r][c * 2] = v.x;
            Bs[r][c * 2 + 1] = v.y;
        }
        __syncthreads();
#pragma unroll
        for (int kk = 0; kk < 16; kk++) {
            float ar[8], br[6];
#pragma unroll
            for (int i = 0; i < 8; i++) ar[i] = As[kk][trow * 8 + i];
#pragma unroll
            for (int j = 0; j < 6; j++) br[j] = Bs[kk][tcol * 6 + j];
#pragma unroll
            for (int i = 0; i < 8; i++)
#pragma unroll
                for (int j = 0; j < 6; j++)
                    acc[i][j] = fmaf(ar[i], br[j], acc[i][j]);
        }
        __syncthreads();
    }
    float* dst = part + (size_t)blockIdx.y * (BLR * 96);
#pragma unroll
    for (int i = 0; i < 8; i++)
#pragma unroll
        for (int j = 0; j < 6; j++)
            dst[(size_t)(bm + trow * 8 + i) * 96 + tcol * 6 + j] = acc[i][j];
}

__global__ void dbc_reduce_kernel(const float* __restrict__ part, float* __restrict__ dbc) {
    int i = blockIdx.x * 256 + threadIdx.x;   // < BLR*96
    float s = 0.f;
#pragma unroll
    for (int k = 0; k < KSPL; k++) s += part[(size_t)k * BLR * 96 + i];
    dbc[i] = s;
}

// ---------------- small fp32 SIMT GEMM, softplus epilogue (W_dt) -----------
__global__ void __launch_bounds__(256)
gemm_softplus_kernel(const float* __restrict__ A, const float* __restrict__ B,
                     const float* __restrict__ bias, float* __restrict__ C,
                     int M, int N, int Kd, int lda, int ldb, int ldc) {
    constexpr int BM = 128, BN = 64, BK = 16;
    __shared__ float As[BK][BM + 4];
    __shared__ float Bs[BK][BN];
    int tid = threadIdx.x;
    int bm = blockIdx.y * BM;
    int bn = blockIdx.x * BN;
    int trow = tid >> 4;
    int tcol = tid & 15;

    float acc[8][4];
#pragma unroll
    for (int i = 0; i < 8; i++)
#pragma unroll
        for (int j = 0; j < 4; j++) acc[i][j] = 0.f;

    for (int k0 = 0; k0 < Kd; k0 += BK) {
#pragma unroll
        for (int i = 0; i < 2; i++) {
            int idx = tid * 2 + i;
            int r = idx >> 2, kq = idx & 3;
            float4 v = *reinterpret_cast<const float4*>(A + (size_t)(bm + r) * lda + k0 + kq * 4);
            As[kq * 4 + 0][r] = v.x;
            As[kq * 4 + 1][r] = v.y;
            As[kq * 4 + 2][r] = v.z;
            As[kq * 4 + 3][r] = v.w;
        }
        {
            int krow = tid >> 4, nq = tid & 15;
            float4 v = *reinterpret_cast<const float4*>(B + (size_t)(k0 + krow) * ldb + bn + nq * 4);
            *reinterpret_cast<float4*>(&Bs[krow][nq * 4]) = v;
        }
        __syncthreads();
#pragma unroll
        for (int kk = 0; kk < BK; kk++) {
            float4 a0 = *reinterpret_cast<const float4*>(&As[kk][trow * 8]);
            float4 a1 = *reinterpret_cast<const float4*>(&As[kk][trow * 8 + 4]);
            float4 b0 = *reinterpret_cast<const float4*>(&Bs[kk][tcol * 4]);
            float ar[8] = {a0.x, a0.y, a0.z, a0.w, a1.x, a1.y, a1.z, a1.w};
            float br[4] = {b0.x, b0.y, b0.z, b0.w};
#pragma unroll
            for (int i = 0; i < 8; i++)
#pragma unroll
                for (int j = 0; j < 4; j++)
                    acc[i][j] = fmaf(ar[i], br[j], acc[i][j]);
        }
        __syncthreads();
    }

#pragma unroll
    for (int i = 0; i < 8; i++) {
        int cr = bm + trow * 8 + i;
#pragma unroll
        for (int j = 0; j < 4; j++) {
            int cc = bn + tcol * 4 + j;
            float v = acc[i][j] + bias[cc];
            C[(size_t)cr * ldc + cc] = (v > 20.f) ? v : log1pf(__expf(v));
        }
    }
}

// ---------------- causal depthwise conv (K=4) + bias + SiLU ----------------
__global__ void conv_silu_kernel(const float* __restrict__ uz, const float* __restrict__ cw,
                                 const float* __restrict__ cb, float* __restrict__ u) {
    int idx = blockIdx.x * blockDim.x + threadIdx.x;
    if (idx >= BLR * EE) return;
    int e = idx % EE;
    int bl = idx / EE;
    int l = bl % LLEN;
    const float* up = uz + (size_t)(bl - l) * (2 * EE) + e;
    float a = cb[e];
#pragma unroll
    for (int k = 0; k < CKW; k++) {
        int lp = l - (CKW - 1) + k;
        if (lp >= 0) a = fmaf(up[(size_t)lp * (2 * EE)], cw[e * CKW + k], a);
    }
    u[idx] = a / (1.f + __expf(-a));
}

// ---------------- selective scan (half y output) ----------------
__global__ void scan_kernel(const float* __restrict__ u, const float* __restrict__ delta,
                            const float* __restrict__ uz, const float* __restrict__ dbc,
                            const float* __restrict__ A_log, const float* __restrict__ Dsk,
                            __half* __restrict__ y) {
    int w = (blockIdx.x * blockDim.x + threadIdx.x) >> 5;
    int lane = threadIdx.x & 31;
    if (w >= BB * EE / 2) return;
    int b = w / (EE / 2);
    int e = (w - b * (EE / 2)) * 2 + (lane >> 4);
    int s = lane & 15;

    float Ae = -__expf(A_log[e * SSZ + s]);
    float dskip = Dsk[e];
    const float* dptr = delta + (size_t)b * LLEN * EE + e;
    const float* uptr = u + (size_t)b * LLEN * EE + e;
    const float* zptr = uz + (size_t)b * LLEN * 2 * EE + EE + e;
    const float* bc = dbc + (size_t)b * LLEN * 96;
    __half* yptr = y + (size_t)b * LLEN * EE + e;

    float hs = 0.f;
    for (int l = 0; l < LLEN; l++) {
        float dlt = dptr[(size_t)l * EE];
        float ul = uptr[(size_t)l * EE];
        float Bv = bc[l * 96 + RRK + s];
        float Cv = bc[l * 96 + RRK + SSZ + s];
        hs = fmaf(__expf(dlt * Ae), hs, (dlt * ul) * Bv);
        float p = hs * Cv;
        p += __shfl_xor_sync(0xffffffffu, p, 8);
        p += __shfl_xor_sync(0xffffffffu, p, 4);
        p += __shfl_xor_sync(0xffffffffu, p, 2);
        p += __shfl_xor_sync(0xffffffffu, p, 1);
        if ((lane & 15) == 0) {
            float z = zptr[(size_t)l * 2 * EE];
            float sz = z / (1.f + __expf(-z));
            yptr[(size_t)l * EE] = __float2half_rn((p + ul * dskip) * sz);
        }
    }
}

// ---------------- reward-weight reduction ----------------
__global__ void wmean_kernel(const float* __restrict__ W_rw, const float* __restrict__ b_rw,
                             float* __restrict__ wm) {
    int d = blockIdx.x * blockDim.x + threadIdx.x;
    if (d < DD) {
        float sum = 0.f;
#pragma unroll
        for (int j = 0; j < SSZ; j++) sum += W_rw[d * SSZ + j];
        wm[d] = sum * (1.f / SSZ);
    }
    if (d == 0) {
        float sum = 0.f;
#pragma unroll
        for (int j = 0; j < SSZ; j++) sum += b_rw[j];
        wm[DD] = sum * (1.f / SSZ);
    }
}

// ---------------- per-row scale ----------------
__global__ void rowscale_kernel(float* __restrict__ h, const float* __restrict__ wm) {
    int row = blockIdx.x;
    float4* hr = reinterpret_cast<float4*>(h + (size_t)row * DD);
    float4 hv = hr[threadIdx.x];
    float4 wv = reinterpret_cast<const float4*>(wm)[threadIdx.x];
    float dot = hv.x * wv.x + hv.y * wv.y + hv.z * wv.z + hv.w * wv.w;
    float s = block_reduce_sum(dot) + wm[DD];
    hr[threadIdx.x] = make_float4(hv.x * s, hv.y * s, hv.z * s, hv.w * s);
}

// ---------------- final LayerNorm (half output) ----------------
__global__ void ln_kernel(const float* __restrict__ h, const float* __restrict__ g,
                          const float* __restrict__ bta, __half* __restrict__ out) {
    int row = blockIdx.x;
    const float4* hr = reinterpret_cast<const float4*>(h + (size_t)row * DD);
    float4 v = hr[threadIdx.x];
    float sm = v.x + v.y + v.z + v.w;
    float sq = v.x * v.x + v.y * v.y + v.z * v.z + v.w * v.w;
    float mu = block_reduce_sum(sm) / (float)DD;
    float var = block_reduce_sum(sq) / (float)DD - mu * mu;
    float inv = rsqrtf(var + 1e-5f);
    float4 gv = reinterpret_cast<const float4*>(g)[threadIdx.x];
    float4 bv = reinterpret_cast<const float4*>(bta)[threadIdx.x];
    __half2* o = reinterpret_cast<__half2*>(out + (size_t)row * DD);
    o[2 * threadIdx.x] = __floats2half2_rn((v.x - mu) * inv * gv.x + bv.x,
                                           (v.y - mu) * inv * gv.y + bv.y);
    o[2 * threadIdx.x + 1] = __floats2half2_rn((v.z - mu) * inv * gv.z + bv.z,
                                               (v.w - mu) * inv * gv.w + bv.w);
}

// ---------------- host orchestration ----------------
extern "C" void kernel_launch(void* const* d_in, const int* in_sizes, int n_in,
                              void* d_out, int out_size) {
    const int* x = (const int*)d_in[0];
    const float* mask = (const float*)d_in[1];
    const float* emb = (const float*)d_in[2];
    const float* norm_w = (const float*)d_in[3];
    const float* W_in = (const float*)d_in[4];
    const float* conv_w = (const float*)d_in[5];
    const float* conv_b = (const float*)d_in[6];
    const float* W_x = (const float*)d_in[7];
    const float* W_dt = (const float*)d_in[8];
    const float* b_dt = (const float*)d_in[9];
    const float* A_log = (const float*)d_in[10];
    const float* D_skip = (const float*)d_in[11];
    const float* W_out = (const float*)d_in[12];
    const float* W_rw = (const float*)d_in[13];
    const float* b_rw = (const float*)d_in[14];
    const float* ln_g = (const float*)d_in[15];
    const float* ln_b = (const float*)d_in[16];
    const float* head_W = (const float*)d_in[17];
    float* out = (float*)d_out;

    float *h_, *uz_, *u_, *dbc_, *dbcp_, *delta_, *wm_;
    __half *xnh_, *yh_, *winh_, *wouth_, *headh_;
    cudaGetSymbolAddress((void**)&h_, g_h);
    cudaGetSymbolAddress((void**)&uz_, g_uz);
    cudaGetSymbolAddress((void**)&u_, g_u);
    cudaGetSymbolAddress((void**)&dbc_, g_dbc);
    cudaGetSymbolAddress((void**)&dbcp_, g_dbc_part);
    cudaGetSymbolAddress((void**)&delta_, g_delta);
    cudaGetSymbolAddress((void**)&wm_, g_wm);
    cudaGetSymbolAddress((void**)&xnh_, g_xn_h);
    cudaGetSymbolAddress((void**)&yh_, g_y_h);
    cudaGetSymbolAddress((void**)&winh_, g_win_h);
    cudaGetSymbolAddress((void**)&wouth_, g_wout_h);
    cudaGetSymbolAddress((void**)&headh_, g_head_h);

    cudaFuncSetAttribute(hgemm<128, 0>, cudaFuncAttributeMaxDynamicSharedMemorySize, HG_SMEM_128);
    cudaFuncSetAttribute(hgemm<64, 1>, cudaFuncAttributeMaxDynamicSharedMemorySize, HG_SMEM_64);

    // convert weights to fp16 scratch
    {
        int n4 = NLAY * DD * 2 * EE / 4;
        f2h_kernel<<<(n4 + 255) / 256, 256>>>(W_in, winh_, n4);
        n4 = NLAY * EE * DD / 4;
        f2h_kernel<<<(n4 + 255) / 256, 256>>>(W_out, wouth_, n4);
        n4 = DD * VV / 4;
        f2h_kernel<<<(n4 + 255) / 256, 256>>>(head_W, headh_, n4);
    }

    embed_kernel<<<BLR, 256>>>(x, mask, emb, h_);

    for (int i = 0; i < NLAY; i++) {
        rmsnorm_kernel<<<BLR, 256>>>(h_, norm_w + (size_t)i * DD, xnh_);

        // uz = xn @ W_in   (2048 x 4096 x 1024)  [fp16 mma, BN=128]
        {
            dim3 g(BLR / 128, (2 * EE) / 128);
            hgemm<128, 0><<<g, 256, HG_SMEM_128>>>(xnh_, winh_ + (size_t)i * DD * 2 * EE,
                                                   uz_, 2 * EE, DD);
        }

        conv_silu_kernel<<<(BLR * EE) / 256, 256>>>(uz_, conv_w + (size_t)i * EE * CKW,
                                                    conv_b + (size_t)i * EE, u_);

        // dbc = u @ W_x    (2048 x 96 x 2048)  [fp32 split-K x8]
        {
            dim3 g(BLR / 128, KSPL);
            wx_splitk_kernel<<<g, 256>>>(u_, W_x + (size_t)i * EE * 96, dbcp_);
            dbc_reduce_kernel<<<(BLR * 96) / 256, 256>>>(dbcp_, dbc_);
        }

        // delta = softplus(dr @ W_dt + b_dt)  (2048 x 2048 x 64)  [fp32 SIMT]
        {
            dim3 g(EE / 64, BLR / 128);
            gemm_softplus_kernel<<<g, 256>>>(dbc_, W_dt + (size_t)i * RRK * EE,
                                             b_dt + (size_t)i * EE, delta_,
                                             BLR, EE, RRK, 96, EE, EE);
        }

        // selective scan + D skip + SiLU gate -> y (fp16)
        scan_kernel<<<(BB * EE / 2) * 32 / 256, 256>>>(u_, delta_, uz_, dbc_,
                                                       A_log + (size_t)i * EE * SSZ,
                                                       D_skip + (size_t)i * EE, yh_);

        // h += y @ W_out   (2048 x 1024 x 2048)  [fp16 mma, BN=64 -> 256 CTAs]
        {
            dim3 g(BLR / 128, DD / 64);
            hgemm<64, 1><<<g, 256, HG_SMEM_64>>>(yh_, wouth_ + (size_t)i * EE * DD, h_, DD, EE);
        }

        // reward-weight scaling
        wmean_kernel<<<DD / 256, 256>>>(W_rw + (size_t)i * DD * SSZ,
                                        b_rw + (size_t)i * SSZ, wm_);
        rowscale_kernel<<<BLR, 256>>>(h_, wm_);
    }

    ln_kernel<<<BLR, 256>>>(h_, ln_g, ln_b, xnh_);

    // logits = xn @ head_W  (2048 x 32000 x 1024)  [fp16 mma, BN=128]
    {
        dim3 g(BLR / 128, VV / 128);
        hgemm<128, 0><<<g, 256, HG_SMEM_128>>>(xnh_, headh_, out, VV, DD);
    }
}

// round 9
// speedup vs baseline: 3.8268x; 1.7418x over previous
#include <cuda_runtime.h>
#include <cuda_fp16.h>
#include <cstdint>

// ---------------- problem constants ----------------
#define BB   2
#define LLEN 1024
#define DD   1024
#define EE   2048
#define SSZ  16
#define RRK  64
#define CKW  4
#define NLAY 4
#define VV   32000
#define BLR  (BB * LLEN)      // 2048 rows
#define KSPL 8                // split-K factor for W_x GEMM

// ---------------- scratch (device globals; no allocation allowed) ----------
__device__ float g_h[BLR * DD];            // residual stream
__device__ float g_uz[BLR * 2 * EE];       // W_in output
__device__ float g_u[BLR * EE];            // post conv+silu
__device__ float g_dbc[BLR * 96];          // dr|B|C (f32, scan reads B,C)
__device__ float g_dbc_part[KSPL * BLR * 96];  // split-K partials
__device__ float g_delta[BLR * EE];        // softplus output
__device__ float g_wm[DD + 1];             // mean-over-S of W_rw, + mean b_rw
// half activations / weights for tensor-core GEMMs
__device__ __half g_xn_h[BLR * DD];        // rmsnorm out / ln out
__device__ __half g_y_h[BLR * EE];         // gated scan output
__device__ __half g_dr_h[BLR * RRK];       // dr (fp16) for W_dt hgemm
__device__ __half g_win_h[NLAY * DD * 2 * EE];
__device__ __half g_wout_h[NLAY * EE * DD];
__device__ __half g_wdt_h[NLAY * RRK * EE];
__device__ __half g_head_h[DD * VV];

// ---------------- small helpers ----------------
__device__ __forceinline__ float block_reduce_sum(float v) {
    __shared__ float red[8];
    __shared__ float tot;
    int lane = threadIdx.x & 31, wid = threadIdx.x >> 5;
#pragma unroll
    for (int o = 16; o; o >>= 1) v += __shfl_xor_sync(0xffffffffu, v, o);
    if (lane == 0) red[wid] = v;
    __syncthreads();
    if (wid == 0) {
        float w = (threadIdx.x < (blockDim.x >> 5)) ? red[threadIdx.x] : 0.f;
#pragma unroll
        for (int o = 4; o; o >>= 1) w += __shfl_xor_sync(0xffffffffu, w, o);
        if (threadIdx.x == 0) tot = w;
    }
    __syncthreads();
    return tot;
}

__device__ __forceinline__ uint32_t smem_u32(const void* p) {
    uint32_t a;
    asm("{ .reg .u64 t; cvta.to.shared.u64 t, %1; cvt.u32.u64 %0, t; }" : "=r"(a) : "l"(p));
    return a;
}
__device__ __forceinline__ void cp16(uint32_t dst, const void* src) {
    asm volatile("cp.async.cg.shared.global [%0], [%1], 16;" :: "r"(dst), "l"(src) : "memory");
}
__device__ __forceinline__ void cp_commit() { asm volatile("cp.async.commit_group;" ::: "memory"); }
template <int N>
__device__ __forceinline__ void cp_wait() { asm volatile("cp.async.wait_group %0;" :: "n"(N) : "memory"); }

__device__ __forceinline__ void ldsm_x4(uint32_t* r, uint32_t addr) {
    asm volatile("ldmatrix.sync.aligned.m8n8.x4.shared.b16 {%0,%1,%2,%3}, [%4];"
                 : "=r"(r[0]), "=r"(r[1]), "=r"(r[2]), "=r"(r[3]) : "r"(addr));
}
__device__ __forceinline__ void ldsm_x4t(uint32_t* r, uint32_t addr) {
    asm volatile("ldmatrix.sync.aligned.m8n8.x4.trans.shared.b16 {%0,%1,%2,%3}, [%4];"
                 : "=r"(r[0]), "=r"(r[1]), "=r"(r[2]), "=r"(r[3]) : "r"(addr));
}
__device__ __forceinline__ void mma_f16(float* c, const uint32_t* a, const uint32_t* b) {
    asm volatile(
        "mma.sync.aligned.m16n8k16.row.col.f32.f16.f16.f32 "
        "{%0,%1,%2,%3}, {%4,%5,%6,%7}, {%8,%9}, {%0,%1,%2,%3};"
        : "+f"(c[0]), "+f"(c[1]), "+f"(c[2]), "+f"(c[3])
        : "r"(a[0]), "r"(a[1]), "r"(a[2]), "r"(a[3]), "r"(b[0]), "r"(b[1]));
}

// ================= fp16 tensor-core GEMM (mma.sync + ldmatrix + cp.async) ====
// C[2048, N] (f32) = A[2048, K] (f16) @ B[K, N] (f16).
// M%128==0, N%BN==0, K%32==0.  BN in {64,128}.
// EPI: 0 = store, 1 = C += result, 2 = softplus(v + bias[col]).
// CTA 128xBNx32, 256 threads, 8 warps (2m x 4n), warp tile 64 x BN/4.
#define HNST 4

template <int BN, int EPI>
__global__ void __launch_bounds__(256, 2)
hgemm(const __half* __restrict__ A, const __half* __restrict__ B,
      const float* __restrict__ bias, float* __restrict__ C, int N, int K) {
    constexpr int ASTG = 128 * 80;            // A: 128 rows x 80B (64B data + pad)
    constexpr int BROW = BN * 2;              // B row bytes
    constexpr int CH = BN / 8;                // 16B chunks per B row
    constexpr int BSTG = 32 * BROW;
    constexpr int STG = ASTG + BSTG;
    constexpr int NT = BN / 32;               // 8-col mma tiles per warp

    extern __shared__ char smem[];
    const uint32_t sb = smem_u32(smem);
    const int tid = threadIdx.x, wid = tid >> 5, lane = tid & 31;
    const int bm = blockIdx.x * 128, bn = blockIdx.y * BN;
    const int wm = (wid >> 2) * 64, wn = (wid & 3) * (BN / 4);
    const int nk = K / 32;

    auto issue_stage = [&](int kb) {
        uint32_t stg = sb + (kb % HNST) * STG;
        const __half* As = A + (size_t)bm * K + kb * 32;
        const __half* Bsrc = B + (size_t)kb * 32 * N + bn;
#pragma unroll
        for (int i = 0; i < 2; i++) {
            int idx = tid * 2 + i;
            int r = idx >> 2, c = idx & 3;
            cp16(stg + r * 80 + c * 16, As + (size_t)r * K + c * 8);
        }
        constexpr int BPER = (32 * CH) / 256;   // 2 (BN=128) or 1 (BN=64)
#pragma unroll
        for (int i = 0; i < BPER; i++) {
            int idx = tid * BPER + i;
            int k = idx / CH, c = idx % CH;
            cp16(stg + ASTG + k * BROW + ((c ^ (k & 7)) << 4),
                 Bsrc + (size_t)k * N + c * 8);
        }
        cp_commit();
    };

    float acc[4][NT][4];
#pragma unroll
    for (int mt = 0; mt < 4; mt++)
#pragma unroll
        for (int nt = 0; nt < NT; nt++)
#pragma unroll
            for (int q = 0; q < 4; q++) acc[mt][nt][q] = 0.f;

    const uint32_t a_off = (uint32_t)((lane & 15) * 80 + (lane >> 4) * 16);
    const int kl = (lane & 7) + ((lane >> 3) & 1) * 8;   // B k-row within 16
    const int nsel = (lane >> 4) * 8;                    // +8 cols for hi half

    issue_stage(0);
    if (nk > 1) issue_stage(1);
    if (nk > 2) issue_stage(2);

    for (int kb = 0; kb < nk; kb++) {
        if (kb < nk - 2)       cp_wait<2>();
        else if (kb == nk - 2) cp_wait<1>();
        else                   cp_wait<0>();
        __syncthreads();
        if (kb + 3 < nk) issue_stage(kb + 3);   // overwrites stage (kb-1)%4 — safe post-sync

        uint32_t Ab = sb + (kb % HNST) * STG;
        uint32_t Bb = Ab + ASTG;
#pragma unroll
        for (int ks = 0; ks < 2; ks++) {
            uint32_t af[4][4], bf[NT * 2];
#pragma unroll
            for (int mt = 0; mt < 4; mt++)
                ldsm_x4(af[mt], Ab + (uint32_t)((wm + mt * 16) * 80) + a_off + ks * 32);
#pragma unroll
            for (int p = 0; p < NT / 2; p++) {
                int n0 = wn + p * 16 + nsel;
                uint32_t nch = (uint32_t)((n0 >> 3) ^ (kl & 7));
                ldsm_x4t(&bf[p * 4], Bb + (uint32_t)((ks * 16 + kl) * BROW) + (nch << 4));
            }
#pragma unroll
            for (int mt = 0; mt < 4; mt++)
#pragma unroll
                for (int nt = 0; nt < NT; nt++)
                    mma_f16(acc[mt][nt], af[mt], &bf[nt * 2]);
        }
    }

    const int gid = lane >> 2, tig = lane & 3;
#pragma unroll
    for (int mt = 0; mt < 4; mt++) {
        int row = bm + wm + mt * 16 + gid;
#pragma unroll
        for (int nt = 0; nt < NT; nt++) {
            int col = bn + wn + nt * 8 + tig * 2;
            float2* c0 = reinterpret_cast<float2*>(C + (size_t)row * N + col);
            float2* c1 = reinterpret_cast<float2*>(C + (size_t)(row + 8) * N + col);
            float2 v0 = make_float2(acc[mt][nt][0], acc[mt][nt][1]);
            float2 v1 = make_float2(acc[mt][nt][2], acc[mt][nt][3]);
            if (EPI == 1) {
                float2 o0 = *c0, o1 = *c1;
                v0.x += o0.x; v0.y += o0.y; v1.x += o1.x; v1.y += o1.y;
            } else if (EPI == 2) {
                float b0 = bias[col], b1 = bias[col + 1];
                v0.x += b0; v0.y += b1; v1.x += b0; v1.y += b1;
                v0.x = (v0.x > 20.f) ? v0.x : log1pf(__expf(v0.x));
                v0.y = (v0.y > 20.f) ? v0.y : log1pf(__expf(v0.y));
                v1.x = (v1.x > 20.f) ? v1.x : log1pf(__expf(v1.x));
                v1.y = (v1.y > 20.f) ? v1.y : log1pf(__expf(v1.y));
            }
            *c0 = v0; *c1 = v1;
        }
    }
}

#define HG_SMEM_128 (HNST * (128 * 80 + 32 * 256))   // 73728
#define HG_SMEM_64  (HNST * (128 * 80 + 32 * 128))   // 57344

// ---------------- fp32 -> fp16 conversion (weights) ----------------
__global__ void f2h_kernel(const float* __restrict__ in, __half* __restrict__ out, int n4) {
    int i = blockIdx.x * blockDim.x + threadIdx.x;
    if (i >= n4) return;
    float4 v = reinterpret_cast<const float4*>(in)[i];
    reinterpret_cast<__half2*>(out)[2 * i] = __floats2half2_rn(v.x, v.y);
    reinterpret_cast<__half2*>(out)[2 * i + 1] = __floats2half2_rn(v.z, v.w);
}

// ---------------- embedding ----------------
__global__ void embed_kernel(const int* __restrict__ x, const float* __restrict__ mask,
                             const float* __restrict__ emb, float* __restrict__ h) {
    int row = blockIdx.x;
    int tok = x[row];
    float m = mask[row];
    const float4* src = reinterpret_cast<const float4*>(emb + (size_t)tok * DD);
    float4* dst = reinterpret_cast<float4*>(h + (size_t)row * DD);
    float4 v = src[threadIdx.x];
    dst[threadIdx.x] = make_float4(v.x * m, v.y * m, v.z * m, v.w * m);
}

// ---------------- RMSNorm (half output) ----------------
__global__ void rmsnorm_kernel(const float* __restrict__ x, const float* __restrict__ w,
                               __half* __restrict__ out) {
    int row = blockIdx.x;
    const float4* xr = reinterpret_cast<const float4*>(x + (size_t)row * DD);
    float4 v = xr[threadIdx.x];
    float ss = v.x * v.x + v.y * v.y + v.z * v.z + v.w * v.w;
    float tot = block_reduce_sum(ss);
    float scale = rsqrtf(tot / (float)DD + 1e-5f);
    float4 wv = reinterpret_cast<const float4*>(w)[threadIdx.x];
    __half2* o = reinterpret_cast<__half2*>(out + (size_t)row * DD);
    o[2 * threadIdx.x] = __floats2half2_rn(v.x * scale * wv.x, v.y * scale * wv.y);
    o[2 * threadIdx.x + 1] = __floats2half2_rn(v.z * scale * wv.z, v.w * scale * wv.w);
}

// ---------------- W_x split-K GEMM ----------------
__global__ void __launch_bounds__(256)
wx_splitk_kernel(const float* __restrict__ A, const float* __restrict__ B,
                 float* __restrict__ part) {
    __shared__ float As[16][132];
    __shared__ float Bs[16][96];
    const int tid = threadIdx.x;
    const int bm = blockIdx.x * 128;
    const int kc = blockIdx.y * (EE / KSPL);
    const int trow = tid >> 4, tcol = tid & 15;

    float acc[8][6];
#pragma unroll
    for (int i = 0; i < 8; i++)
#pragma unroll
        for (int j = 0; j < 6; j++) acc[i][j] = 0.f;

    for (int k0 = 0; k0 < EE / KSPL; k0 += 16) {
#pragma unroll
        for (int i = 0; i < 2; i++) {
            int idx = tid * 2 + i;
            int r = idx >> 2, kq = idx & 3;
            float4 v = *reinterpret_cast<const float4*>(
                A + (size_t)(bm + r) * EE + kc + k0 + kq * 4);
            As[kq * 4 + 0][r] = v.x;
            As[kq * 4 + 1][r] = v.y;
            As[kq * 4 + 2][r] = v.z;
            As[kq * 4 + 3][r] = v.w;
        }
#pragma unroll
        for (int i = 0; i < 3; i++) {
            int idx = tid + i * 256;
            int r = idx / 48, c = idx % 48;
            float2 v = *reinterpret_cast<const float2*>(B + (size_t)(kc + k0 + r) * 96 + c * 2);
            Bs[r][c * 2] = v.x;
            Bs[r][c * 2 + 1] = v.y;
        }
        __syncthreads();
#pragma unroll
        for (int kk = 0; kk < 16; kk++) {
            float ar[8], br[6];
#pragma unroll
            for (int i = 0; i < 8; i++) ar[i] = As[kk][trow * 8 + i];
#pragma unroll
            for (int j = 0; j < 6; j++) br[j] = Bs[kk][tcol * 6 + j];
#pragma unroll
            for (int i = 0; i < 8; i++)
#pragma unroll
                for (int j = 0; j < 6; j++)
                    acc[i][j] = fmaf(ar[i], br[j], acc[i][j]);
        }
        __syncthreads();
    }
    float* dst = part + (size_t)blockIdx.y * (BLR * 96);
#pragma unroll
    for (int i = 0; i < 8; i++)
#pragma unroll
        for (int j = 0; j < 6; j++)
            dst[(size_t)(bm + trow * 8 + i) * 96 + tcol * 6 + j] = acc[i][j];
}

// reduce partials -> dbc (f32) and dr (fp16, cols 0..63)
__global__ void dbc_reduce_kernel(const float* __restrict__ part, float* __restrict__ dbc,
                                  __half* __restrict__ drh) {
    int i = blockIdx.x * 256 + threadIdx.x;   // < BLR*96
    float s = 0.f;
#pragma unroll
    for (int k = 0; k < KSPL; k++) s += part[(size_t)k * BLR * 96 + i];
    dbc[i] = s;
    int col = i % 96;
    if (col < RRK) {
        int row = i / 96;
        drh[row * RRK + col] = __float2half_rn(s);
    }
}

// ---------------- causal depthwise conv (K=4) + bias + SiLU ----------------
__global__ void conv_silu_kernel(const float* __restrict__ uz, const float* __restrict__ cw,
                                 const float* __restrict__ cb, float* __restrict__ u) {
    int idx = blockIdx.x * blockDim.x + threadIdx.x;
    if (idx >= BLR * EE) return;
    int e = idx % EE;
    int bl = idx / EE;
    int l = bl % LLEN;
    const float* up = uz + (size_t)(bl - l) * (2 * EE) + e;
    float a = cb[e];
#pragma unroll
    for (int k = 0; k < CKW; k++) {
        int lp = l - (CKW - 1) + k;
        if (lp >= 0) a = fmaf(up[(size_t)lp * (2 * EE)], cw[e * CKW + k], a);
    }
    u[idx] = a / (1.f + __expf(-a));
}

// ---------------- selective scan, unrolled x4 with batched loads -----------
__global__ void scan_kernel(const float* __restrict__ u, const float* __restrict__ delta,
                            const float* __restrict__ uz, const float* __restrict__ dbc,
                            const float* __restrict__ A_log, const float* __restrict__ Dsk,
                            __half* __restrict__ y) {
    int w = (blockIdx.x * blockDim.x + threadIdx.x) >> 5;
    int lane = threadIdx.x & 31;
    if (w >= BB * EE / 2) return;
    int b = w / (EE / 2);
    int e = (w - b * (EE / 2)) * 2 + (lane >> 4);
    int s = lane & 15;

    float Ae = -__expf(A_log[e * SSZ + s]);
    float dskip = Dsk[e];
    const float* dptr = delta + (size_t)b * LLEN * EE + e;
    const float* uptr = u + (size_t)b * LLEN * EE + e;
    const float* zptr = uz + (size_t)b * LLEN * 2 * EE + EE + e;
    const float* bc = dbc + (size_t)b * LLEN * 96;
    __half* yptr = y + (size_t)b * LLEN * EE + e;

    float hs = 0.f;
    for (int l0 = 0; l0 < LLEN; l0 += 4) {
        float dlt[4], ul[4], Bv[4], Cv[4], zz[4];
        // batch all global loads (MLP=20)
#pragma unroll
        for (int i = 0; i < 4; i++) dlt[i] = dptr[(size_t)(l0 + i) * EE];
#pragma unroll
        for (int i = 0; i < 4; i++) ul[i] = uptr[(size_t)(l0 + i) * EE];
#pragma unroll
        for (int i = 0; i < 4; i++) Bv[i] = bc[(l0 + i) * 96 + RRK + s];
#pragma unroll
        for (int i = 0; i < 4; i++) Cv[i] = bc[(l0 + i) * 96 + RRK + SSZ + s];
#pragma unroll
        for (int i = 0; i < 4; i++) zz[i] = zptr[(size_t)(l0 + i) * 2 * EE];

        float da[4];
#pragma unroll
        for (int i = 0; i < 4; i++) da[i] = __expf(dlt[i] * Ae);

        float p[4];
#pragma unroll
        for (int i = 0; i < 4; i++) {
            hs = fmaf(da[i], hs, (dlt[i] * ul[i]) * Bv[i]);
            p[i] = hs * Cv[i];
        }
#pragma unroll
        for (int i = 0; i < 4; i++) {
            p[i] += __shfl_xor_sync(0xffffffffu, p[i], 8);
            p[i] += __shfl_xor_sync(0xffffffffu, p[i], 4);
            p[i] += __shfl_xor_sync(0xffffffffu, p[i], 2);
            p[i] += __shfl_xor_sync(0xffffffffu, p[i], 1);
        }
        if ((lane & 15) == 0) {
#pragma unroll
            for (int i = 0; i < 4; i++) {
                float sz = zz[i] / (1.f + __expf(-zz[i]));
                yptr[(size_t)(l0 + i) * EE] = __float2half_rn((p[i] + ul[i] * dskip) * sz);
            }
        }
    }
}

// ---------------- reward-weight reduction ----------------
__global__ void wmean_kernel(const float* __restrict__ W_rw, const float* __restrict__ b_rw,
                             float* __restrict__ wm) {
    int d = blockIdx.x * blockDim.x + threadIdx.x;
    if (d < DD) {
        float sum = 0.f;
#pragma unroll
        for (int j = 0; j < SSZ; j++) sum += W_rw[d * SSZ + j];
        wm[d] = sum * (1.f / SSZ);
    }
    if (d == 0) {
        float sum = 0.f;
#pragma unroll
        for (int j = 0; j < SSZ; j++) sum += b_rw[j];
        wm[DD] = sum * (1.f / SSZ);
    }
}

// ---------------- per-row scale ----------------
__global__ void rowscale_kernel(float* __restrict__ h, const float* __restrict__ wm) {
    int row = blockIdx.x;
    float4* hr = reinterpret_cast<float4*>(h + (size_t)row * DD);
    float4 hv = hr[threadIdx.x];
    float4 wv = reinterpret_cast<const float4*>(wm)[threadIdx.x];
    float dot = hv.x * wv.x + hv.y * wv.y + hv.z * wv.z + hv.w * wv.w;
    float s = block_reduce_sum(dot) + wm[DD];
    hr[threadIdx.x] = make_float4(hv.x * s, hv.y * s, hv.z * s, hv.w * s);
}

// ---------------- final LayerNorm (half output) ----------------
__global__ void ln_kernel(const float* __restrict__ h, const float* __restrict__ g,
                          const float* __restrict__ bta, __half* __restrict__ out) {
    int row = blockIdx.x;
    const float4* hr = reinterpret_cast<const float4*>(h + (size_t)row * DD);
    float4 v = hr[threadIdx.x];
    float sm = v.x + v.y + v.z + v.w;
    float sq = v.x * v.x + v.y * v.y + v.z * v.z + v.w * v.w;
    float mu = block_reduce_sum(sm) / (float)DD;
    float var = block_reduce_sum(sq) / (float)DD - mu * mu;
    float inv = rsqrtf(var + 1e-5f);
    float4 gv = reinterpret_cast<const float4*>(g)[threadIdx.x];
    float4 bv = reinterpret_cast<const float4*>(bta)[threadIdx.x];
    __half2* o = reinterpret_cast<__half2*>(out + (size_t)row * DD);
    o[2 * threadIdx.x] = __floats2half2_rn((v.x - mu) * inv * gv.x + bv.x,
                                           (v.y - mu) * inv * gv.y + bv.y);
    o[2 * threadIdx.x + 1] = __floats2half2_rn((v.z - mu) * inv * gv.z + bv.z,
                                               (v.w - mu) * inv * gv.w + bv.w);
}

// ---------------- host orchestration ----------------
extern "C" void kernel_launch(void* const* d_in, const int* in_sizes, int n_in,
                              void* d_out, int out_size) {
    const int* x = (const int*)d_in[0];
    const float* mask = (const float*)d_in[1];
    const float* emb = (const float*)d_in[2];
    const float* norm_w = (const float*)d_in[3];
    const float* W_in = (const float*)d_in[4];
    const float* conv_w = (const float*)d_in[5];
    const float* conv_b = (const float*)d_in[6];
    const float* W_x = (const float*)d_in[7];
    const float* W_dt = (const float*)d_in[8];
    const float* b_dt = (const float*)d_in[9];
    const float* A_log = (const float*)d_in[10];
    const float* D_skip = (const float*)d_in[11];
    const float* W_out = (const float*)d_in[12];
    const float* W_rw = (const float*)d_in[13];
    const float* b_rw = (const float*)d_in[14];
    const float* ln_g = (const float*)d_in[15];
    const float* ln_b = (const float*)d_in[16];
    const float* head_W = (const float*)d_in[17];
    float* out = (float*)d_out;

    float *h_, *uz_, *u_, *dbc_, *dbcp_, *delta_, *wm_;
    __half *xnh_, *yh_, *drh_, *winh_, *wouth_, *wdth_, *headh_;
    cudaGetSymbolAddress((void**)&h_, g_h);
    cudaGetSymbolAddress((void**)&uz_, g_uz);
    cudaGetSymbolAddress((void**)&u_, g_u);
    cudaGetSymbolAddress((void**)&dbc_, g_dbc);
    cudaGetSymbolAddress((void**)&dbcp_, g_dbc_part);
    cudaGetSymbolAddress((void**)&delta_, g_delta);
    cudaGetSymbolAddress((void**)&wm_, g_wm);
    cudaGetSymbolAddress((void**)&xnh_, g_xn_h);
    cudaGetSymbolAddress((void**)&yh_, g_y_h);
    cudaGetSymbolAddress((void**)&drh_, g_dr_h);
    cudaGetSymbolAddress((void**)&winh_, g_win_h);
    cudaGetSymbolAddress((void**)&wouth_, g_wout_h);
    cudaGetSymbolAddress((void**)&wdth_, g_wdt_h);
    cudaGetSymbolAddress((void**)&headh_, g_head_h);

    cudaFuncSetAttribute(hgemm<128, 0>, cudaFuncAttributeMaxDynamicSharedMemorySize, HG_SMEM_128);
    cudaFuncSetAttribute(hgemm<128, 2>, cudaFuncAttributeMaxDynamicSharedMemorySize, HG_SMEM_128);
    cudaFuncSetAttribute(hgemm<64, 1>, cudaFuncAttributeMaxDynamicSharedMemorySize, HG_SMEM_64);

    // convert weights to fp16 scratch
    {
        int n4 = NLAY * DD * 2 * EE / 4;
        f2h_kernel<<<(n4 + 255) / 256, 256>>>(W_in, winh_, n4);
        n4 = NLAY * EE * DD / 4;
        f2h_kernel<<<(n4 + 255) / 256, 256>>>(W_out, wouth_, n4);
        n4 = NLAY * RRK * EE / 4;
        f2h_kernel<<<(n4 + 255) / 256, 256>>>(W_dt, wdth_, n4);
        n4 = DD * VV / 4;
        f2h_kernel<<<(n4 + 255) / 256, 256>>>(head_W, headh_, n4);
    }

    embed_kernel<<<BLR, 256>>>(x, mask, emb, h_);

    for (int i = 0; i < NLAY; i++) {
        rmsnorm_kernel<<<BLR, 256>>>(h_, norm_w + (size_t)i * DD, xnh_);

        // uz = xn @ W_in   (2048 x 4096 x 1024)  [fp16 mma, BN=128]
        {
            dim3 g(BLR / 128, (2 * EE) / 128);
            hgemm<128, 0><<<g, 256, HG_SMEM_128>>>(xnh_, winh_ + (size_t)i * DD * 2 * EE,
                                                   nullptr, uz_, 2 * EE, DD);
        }

        conv_silu_kernel<<<(BLR * EE) / 256, 256>>>(uz_, conv_w + (size_t)i * EE * CKW,
                                                    conv_b + (size_t)i * EE, u_);

        // dbc = u @ W_x    (2048 x 96 x 2048)  [fp32 split-K x8] -> dbc f32 + dr fp16
        {
            dim3 g(BLR / 128, KSPL);
            wx_splitk_kernel<<<g, 256>>>(u_, W_x + (size_t)i * EE * 96, dbcp_);
            dbc_reduce_kernel<<<(BLR * 96) / 256, 256>>>(dbcp_, dbc_, drh_);
        }

        // delta = softplus(dr @ W_dt + b_dt)  (2048 x 2048 x 64)  [fp16 mma, softplus epi]
        {
            dim3 g(BLR / 128, EE / 128);
            hgemm<128, 2><<<g, 256, HG_SMEM_128>>>(drh_, wdth_ + (size_t)i * RRK * EE,
                                                   b_dt + (size_t)i * EE, delta_, EE, RRK);
        }

        // selective scan + D skip + SiLU gate -> y (fp16)
        scan_kernel<<<(BB * EE / 2) * 32 / 256, 256>>>(u_, delta_, uz_, dbc_,
                                                       A_log + (size_t)i * EE * SSZ,
                                                       D_skip + (size_t)i * EE, yh_);

        // h += y @ W_out   (2048 x 1024 x 2048)  [fp16 mma, BN=64]
        {
            dim3 g(BLR / 128, DD / 64);
            hgemm<64, 1><<<g, 256, HG_SMEM_64>>>(yh_, wouth_ + (size_t)i * EE * DD,
                                                 nullptr, h_, DD, EE);
        }

        // reward-weight scaling
        wmean_kernel<<<DD / 256, 256>>>(W_rw + (size_t)i * DD * SSZ,
                                        b_rw + (size_t)i * SSZ, wm_);
        rowscale_kernel<<<BLR, 256>>>(h_, wm_);
    }

    ln_kernel<<<BLR, 256>>>(h_, ln_g, ln_b, xnh_);

    // logits = xn @ head_W  (2048 x 32000 x 1024)  [fp16 mma, BN=128]
    {
        dim3 g(BLR / 128, VV / 128);
        hgemm<128, 0><<<g, 256, HG_SMEM_128>>>(xnh_, headh_, nullptr, out, VV, DD);
    }
}

// round 10
// speedup vs baseline: 3.9169x; 1.0235x over previous
#include <cuda_runtime.h>
#include <cuda_fp16.h>
#include <cstdint>

// ---------------- problem constants ----------------
#define BB   2
#define LLEN 1024
#define DD   1024
#define EE   2048
#define SSZ  16
#define RRK  64
#define CKW  4
#define NLAY 4
#define VV   32000
#define BLR  (BB * LLEN)      // 2048 rows
#define KSPL 8                // split-K factor for W_x GEMM

// ---------------- scratch (device globals; no allocation allowed) ----------
__device__ float g_h[BLR * DD];            // residual stream
__device__ float g_uz[BLR * 2 * EE];       // W_in output
__device__ float g_u[BLR * EE];            // post conv+silu
__device__ float g_dbc[BLR * 96];          // dr|B|C (f32, scan reads B,C)
__device__ float g_dbc_part[KSPL * BLR * 96];  // split-K partials
__device__ float g_delta[BLR * EE];        // softplus output
__device__ float g_wm[DD + 1];             // mean-over-S of W_rw, + mean b_rw
// half activations / weights for tensor-core GEMMs
__device__ __half g_xn_h[BLR * DD];        // rmsnorm out / ln out
__device__ __half g_y_h[BLR * EE];         // gated scan output
__device__ __half g_dr_h[BLR * RRK];       // dr (fp16) for W_dt hgemm
__device__ __half g_win_h[NLAY * DD * 2 * EE];
__device__ __half g_wout_h[NLAY * EE * DD];
__device__ __half g_wdt_h[NLAY * RRK * EE];
__device__ __half g_head_h[DD * VV];

// ---------------- small helpers ----------------
__device__ __forceinline__ float block_reduce_sum(float v) {
    __shared__ float red[8];
    __shared__ float tot;
    int lane = threadIdx.x & 31, wid = threadIdx.x >> 5;
#pragma unroll
    for (int o = 16; o; o >>= 1) v += __shfl_xor_sync(0xffffffffu, v, o);
    if (lane == 0) red[wid] = v;
    __syncthreads();
    if (wid == 0) {
        float w = (threadIdx.x < (blockDim.x >> 5)) ? red[threadIdx.x] : 0.f;
#pragma unroll
        for (int o = 4; o; o >>= 1) w += __shfl_xor_sync(0xffffffffu, w, o);
        if (threadIdx.x == 0) tot = w;
    }
    __syncthreads();
    return tot;
}

__device__ __forceinline__ uint32_t smem_u32(const void* p) {
    uint32_t a;
    asm("{ .reg .u64 t; cvta.to.shared.u64 t, %1; cvt.u32.u64 %0, t; }" : "=r"(a) : "l"(p));
    return a;
}
__device__ __forceinline__ void cp16(uint32_t dst, const void* src) {
    asm volatile("cp.async.cg.shared.global [%0], [%1], 16;" :: "r"(dst), "l"(src) : "memory");
}
__device__ __forceinline__ void cp_commit() { asm volatile("cp.async.commit_group;" ::: "memory"); }
template <int N>
__device__ __forceinline__ void cp_wait() { asm volatile("cp.async.wait_group %0;" :: "n"(N) : "memory"); }

__device__ __forceinline__ void ldsm_x4(uint32_t* r, uint32_t addr) {
    asm volatile("ldmatrix.sync.aligned.m8n8.x4.shared.b16 {%0,%1,%2,%3}, [%4];"
                 : "=r"(r[0]), "=r"(r[1]), "=r"(r[2]), "=r"(r[3]) : "r"(addr));
}
__device__ __forceinline__ void ldsm_x4t(uint32_t* r, uint32_t addr) {
    asm volatile("ldmatrix.sync.aligned.m8n8.x4.trans.shared.b16 {%0,%1,%2,%3}, [%4];"
                 : "=r"(r[0]), "=r"(r[1]), "=r"(r[2]), "=r"(r[3]) : "r"(addr));
}
__device__ __forceinline__ void mma_f16(float* c, const uint32_t* a, const uint32_t* b) {
    asm volatile(
        "mma.sync.aligned.m16n8k16.row.col.f32.f16.f16.f32 "
        "{%0,%1,%2,%3}, {%4,%5,%6,%7}, {%8,%9}, {%0,%1,%2,%3};"
        : "+f"(c[0]), "+f"(c[1]), "+f"(c[2]), "+f"(c[3])
        : "r"(a[0]), "r"(a[1]), "r"(a[2]), "r"(a[3]), "r"(b[0]), "r"(b[1]));
}

// ================= fp16 tensor-core GEMM (mma.sync + ldmatrix + cp.async) ====
// C[2048, N] (f32) = A[2048, K] (f16) @ B[K, N] (f16).
// M%128==0, N%BN==0, K%32==0.  BN in {64,128}.
// EPI: 0 = store, 1 = C += result, 2 = softplus(v + bias[col]).
// CTA 128xBNx32, 256 threads, 8 warps (2m x 4n), warp tile 64 x BN/4.
// Inner loop software-pipelined: B frags first, A frags double-buffered so
// each ldmatrix's latency hides under the previous fragment group's mmas.
#define HNST 4

template <int BN, int EPI>
__global__ void __launch_bounds__(256, 2)
hgemm(const __half* __restrict__ A, const __half* __restrict__ B,
      const float* __restrict__ bias, float* __restrict__ C, int N, int K) {
    constexpr int ASTG = 128 * 80;            // A: 128 rows x 80B (64B data + pad)
    constexpr int BROW = BN * 2;              // B row bytes
    constexpr int CH = BN / 8;                // 16B chunks per B row
    constexpr int BSTG = 32 * BROW;
    constexpr int STG = ASTG + BSTG;
    constexpr int NT = BN / 32;               // 8-col mma tiles per warp

    extern __shared__ char smem[];
    const uint32_t sb = smem_u32(smem);
    const int tid = threadIdx.x, wid = tid >> 5, lane = tid & 31;
    const int bm = blockIdx.x * 128, bn = blockIdx.y * BN;
    const int wm = (wid >> 2) * 64, wn = (wid & 3) * (BN / 4);
    const int nk = K / 32;

    auto issue_stage = [&](int kb) {
        uint32_t stg = sb + (kb % HNST) * STG;
        const __half* As = A + (size_t)bm * K + kb * 32;
        const __half* Bsrc = B + (size_t)kb * 32 * N + bn;
#pragma unroll
        for (int i = 0; i < 2; i++) {
            int idx = tid * 2 + i;
            int r = idx >> 2, c = idx & 3;
            cp16(stg + r * 80 + c * 16, As + (size_t)r * K + c * 8);
        }
        constexpr int BPER = (32 * CH) / 256;   // 2 (BN=128) or 1 (BN=64)
#pragma unroll
        for (int i = 0; i < BPER; i++) {
            int idx = tid * BPER + i;
            int k = idx / CH, c = idx % CH;
            cp16(stg + ASTG + k * BROW + ((c ^ (k & 7)) << 4),
                 Bsrc + (size_t)k * N + c * 8);
        }
        cp_commit();
    };

    float acc[4][NT][4];
#pragma unroll
    for (int mt = 0; mt < 4; mt++)
#pragma unroll
        for (int nt = 0; nt < NT; nt++)
#pragma unroll
            for (int q = 0; q < 4; q++) acc[mt][nt][q] = 0.f;

    const uint32_t a_off = (uint32_t)((lane & 15) * 80 + (lane >> 4) * 16);
    const int kl = (lane & 7) + ((lane >> 3) & 1) * 8;   // B k-row within 16
    const int nsel = (lane >> 4) * 8;                    // +8 cols for hi half

    issue_stage(0);
    if (nk > 1) issue_stage(1);
    if (nk > 2) issue_stage(2);

    for (int kb = 0; kb < nk; kb++) {
        if (kb < nk - 2)       cp_wait<2>();
        else if (kb == nk - 2) cp_wait<1>();
        else                   cp_wait<0>();
        __syncthreads();
        if (kb + 3 < nk) issue_stage(kb + 3);   // overwrites stage (kb-1)%4 — safe post-sync

        uint32_t Ab = sb + (kb % HNST) * STG;
        uint32_t Bb = Ab + ASTG;
#pragma unroll
        for (int ks = 0; ks < 2; ks++) {
            uint32_t bf[NT * 2];
#pragma unroll
            for (int p = 0; p < NT / 2; p++) {
                int n0 = wn + p * 16 + nsel;
                uint32_t nch = (uint32_t)((n0 >> 3) ^ (kl & 7));
                ldsm_x4t(&bf[p * 4], Bb + (uint32_t)((ks * 16 + kl) * BROW) + (nch << 4));
            }
            // A double-buffer: prefetch next mt's fragments before current mmas
            uint32_t afA[4], afB[4];
            ldsm_x4(afA, Ab + (uint32_t)((wm + 0 * 16) * 80) + a_off + ks * 32);
#pragma unroll
            for (int mt = 0; mt < 4; mt++) {
                uint32_t* cur = (mt & 1) ? afB : afA;
                uint32_t* nxt = (mt & 1) ? afA : afB;
                if (mt < 3)
                    ldsm_x4(nxt, Ab + (uint32_t)((wm + (mt + 1) * 16) * 80) + a_off + ks * 32);
#pragma unroll
                for (int nt = 0; nt < NT; nt++)
                    mma_f16(acc[mt][nt], cur, &bf[nt * 2]);
            }
        }
    }

    const int gid = lane >> 2, tig = lane & 3;
#pragma unroll
    for (int mt = 0; mt < 4; mt++) {
        int row = bm + wm + mt * 16 + gid;
#pragma unroll
        for (int nt = 0; nt < NT; nt++) {
            int col = bn + wn + nt * 8 + tig * 2;
            float2* c0 = reinterpret_cast<float2*>(C + (size_t)row * N + col);
            float2* c1 = reinterpret_cast<float2*>(C + (size_t)(row + 8) * N + col);
            float2 v0 = make_float2(acc[mt][nt][0], acc[mt][nt][1]);
            float2 v1 = make_float2(acc[mt][nt][2], acc[mt][nt][3]);
            if (EPI == 1) {
                float2 o0 = *c0, o1 = *c1;
                v0.x += o0.x; v0.y += o0.y; v1.x += o1.x; v1.y += o1.y;
            } else if (EPI == 2) {
                float b0 = bias[col], b1 = bias[col + 1];
                v0.x += b0; v0.y += b1; v1.x += b0; v1.y += b1;
                v0.x = (v0.x > 20.f) ? v0.x : log1pf(__expf(v0.x));
                v0.y = (v0.y > 20.f) ? v0.y : log1pf(__expf(v0.y));
                v1.x = (v1.x > 20.f) ? v1.x : log1pf(__expf(v1.x));
                v1.y = (v1.y > 20.f) ? v1.y : log1pf(__expf(v1.y));
            }
            *c0 = v0; *c1 = v1;
        }
    }
}

#define HG_SMEM_128 (HNST * (128 * 80 + 32 * 256))   // 73728
#define HG_SMEM_64  (HNST * (128 * 80 + 32 * 128))   // 57344

// ---------------- fp32 -> fp16 conversion (weights) ----------------
__global__ void f2h_kernel(const float* __restrict__ in, __half* __restrict__ out, int n4) {
    int i = blockIdx.x * blockDim.x + threadIdx.x;
    if (i >= n4) return;
    float4 v = reinterpret_cast<const float4*>(in)[i];
    reinterpret_cast<__half2*>(out)[2 * i] = __floats2half2_rn(v.x, v.y);
    reinterpret_cast<__half2*>(out)[2 * i + 1] = __floats2half2_rn(v.z, v.w);
}

// ---------------- embedding ----------------
__global__ void embed_kernel(const int* __restrict__ x, const float* __restrict__ mask,
                             const float* __restrict__ emb, float* __restrict__ h) {
    int row = blockIdx.x;
    int tok = x[row];
    float m = mask[row];
    const float4* src = reinterpret_cast<const float4*>(emb + (size_t)tok * DD);
    float4* dst = reinterpret_cast<float4*>(h + (size_t)row * DD);
    float4 v = src[threadIdx.x];
    dst[threadIdx.x] = make_float4(v.x * m, v.y * m, v.z * m, v.w * m);
}

// ---------------- RMSNorm (half output) ----------------
__global__ void rmsnorm_kernel(const float* __restrict__ x, const float* __restrict__ w,
                               __half* __restrict__ out) {
    int row = blockIdx.x;
    const float4* xr = reinterpret_cast<const float4*>(x + (size_t)row * DD);
    float4 v = xr[threadIdx.x];
    float ss = v.x * v.x + v.y * v.y + v.z * v.z + v.w * v.w;
    float tot = block_reduce_sum(ss);
    float scale = rsqrtf(tot / (float)DD + 1e-5f);
    float4 wv = reinterpret_cast<const float4*>(w)[threadIdx.x];
    __half2* o = reinterpret_cast<__half2*>(out + (size_t)row * DD);
    o[2 * threadIdx.x] = __floats2half2_rn(v.x * scale * wv.x, v.y * scale * wv.y);
    o[2 * threadIdx.x + 1] = __floats2half2_rn(v.z * scale * wv.z, v.w * scale * wv.w);
}

// ---- fused: h *= rowscale; then RMSNorm(h) -> xnh (next layer input) ------
__global__ void rowscale_rms_kernel(float* __restrict__ h, const float* __restrict__ wm,
                                    const float* __restrict__ nw, __half* __restrict__ out) {
    int row = blockIdx.x;
    float4* hr = reinterpret_cast<float4*>(h + (size_t)row * DD);
    float4 hv = hr[threadIdx.x];
    float4 wv = reinterpret_cast<const float4*>(wm)[threadIdx.x];
    float dot = hv.x * wv.x + hv.y * wv.y + hv.z * wv.z + hv.w * wv.w;
    float s = block_reduce_sum(dot) + wm[DD];
    hv.x *= s; hv.y *= s; hv.z *= s; hv.w *= s;
    hr[threadIdx.x] = hv;
    float ss = hv.x * hv.x + hv.y * hv.y + hv.z * hv.z + hv.w * hv.w;
    float tot = block_reduce_sum(ss);
    float scale = rsqrtf(tot / (float)DD + 1e-5f);
    float4 nwv = reinterpret_cast<const float4*>(nw)[threadIdx.x];
    __half2* o = reinterpret_cast<__half2*>(out + (size_t)row * DD);
    o[2 * threadIdx.x] = __floats2half2_rn(hv.x * scale * nwv.x, hv.y * scale * nwv.y);
    o[2 * threadIdx.x + 1] = __floats2half2_rn(hv.z * scale * nwv.z, hv.w * scale * nwv.w);
}

// ---- fused: h *= rowscale; then LayerNorm(h) -> xnh (head input) ----------
__global__ void rowscale_ln_kernel(const float* __restrict__ h, const float* __restrict__ wm,
                                   const float* __restrict__ g, const float* __restrict__ bta,
                                   __half* __restrict__ out) {
    int row = blockIdx.x;
    const float4* hr = reinterpret_cast<const float4*>(h + (size_t)row * DD);
    float4 hv = hr[threadIdx.x];
    float4 wv = reinterpret_cast<const float4*>(wm)[threadIdx.x];
    float dot = hv.x * wv.x + hv.y * wv.y + hv.z * wv.z + hv.w * wv.w;
    float s = block_reduce_sum(dot) + wm[DD];
    hv.x *= s; hv.y *= s; hv.z *= s; hv.w *= s;
    float sm = hv.x + hv.y + hv.z + hv.w;
    float sq = hv.x * hv.x + hv.y * hv.y + hv.z * hv.z + hv.w * hv.w;
    float mu = block_reduce_sum(sm) / (float)DD;
    float var = block_reduce_sum(sq) / (float)DD - mu * mu;
    float inv = rsqrtf(var + 1e-5f);
    float4 gv = reinterpret_cast<const float4*>(g)[threadIdx.x];
    float4 bv = reinterpret_cast<const float4*>(bta)[threadIdx.x];
    __half2* o = reinterpret_cast<__half2*>(out + (size_t)row * DD);
    o[2 * threadIdx.x] = __floats2half2_rn((hv.x - mu) * inv * gv.x + bv.x,
                                           (hv.y - mu) * inv * gv.y + bv.y);
    o[2 * threadIdx.x + 1] = __floats2half2_rn((hv.z - mu) * inv * gv.z + bv.z,
                                               (hv.w - mu) * inv * gv.w + bv.w);
}

// ---------------- W_x split-K GEMM ----------------
__global__ void __launch_bounds__(256)
wx_splitk_kernel(const float* __restrict__ A, const float* __restrict__ B,
                 float* __restrict__ part) {
    __shared__ float As[16][132];
    __shared__ float Bs[16][96];
    const int tid = threadIdx.x;
    const int bm = blockIdx.x * 128;
    const int kc = blockIdx.y * (EE / KSPL);
    const int trow = tid >> 4, tcol = tid & 15;

    float acc[8][6];
#pragma unroll
    for (int i = 0; i < 8; i++)
#pragma unroll
        for (int j = 0; j < 6; j++) acc[i][j] = 0.f;

    for (int k0 = 0; k0 < EE / KSPL; k0 += 16) {
#pragma unroll
        for (int i = 0; i < 2; i++) {
            int idx = tid * 2 + i;
            int r = idx >> 2, kq = idx & 3;
            float4 v = *reinterpret_cast<const float4*>(
                A + (size_t)(bm + r) * EE + kc + k0 + kq * 4);
            As[kq * 4 + 0][r] = v.x;
            As[kq * 4 + 1][r] = v.y;
            As[kq * 4 + 2][r] = v.z;
            As[kq * 4 + 3][r] = v.w;
        }
#pragma unroll
        for (int i = 0; i < 3; i++) {
            int idx = tid + i * 256;
            int r = idx / 48, c = idx % 48;
            float2 v = *reinterpret_cast<const float2*>(B + (size_t)(kc + k0 + r) * 96 + c * 2);
            Bs[r][c * 2] = v.x;
            Bs[r][c * 2 + 1] = v.y;
        }
        __syncthreads();
#pragma unroll
        for (int kk = 0; kk < 16; kk++) {
            float ar[8], br[6];
#pragma unroll
            for (int i = 0; i < 8; i++) ar[i] = As[kk][trow * 8 + i];
#pragma unroll
            for (int j = 0; j < 6; j++) br[j] = Bs[kk][tcol * 6 + j];
#pragma unroll
            for (int i = 0; i < 8; i++)
#pragma unroll
                for (int j = 0; j < 6; j++)
                    acc[i][j] = fmaf(ar[i], br[j], acc[i][j]);
        }
        __syncthreads();
    }
    float* dst = part + (size_t)blockIdx.y * (BLR * 96);
#pragma unroll
    for (int i = 0; i < 8; i++)
#pragma unroll
        for (int j = 0; j < 6; j++)
            dst[(size_t)(bm + trow * 8 + i) * 96 + tcol * 6 + j] = acc[i][j];
}

// reduce partials -> dbc (f32) and dr (fp16, cols 0..63)
__global__ void dbc_reduce_kernel(const float* __restrict__ part, float* __restrict__ dbc,
                                  __half* __restrict__ drh) {
    int i = blockIdx.x * 256 + threadIdx.x;   // < BLR*96
    float s = 0.f;
#pragma unroll
    for (int k = 0; k < KSPL; k++) s += part[(size_t)k * BLR * 96 + i];
    dbc[i] = s;
    int col = i % 96;
    if (col < RRK) {
        int row = i / 96;
        drh[row * RRK + col] = __float2half_rn(s);
    }
}

// ---------------- causal depthwise conv (K=4) + bias + SiLU ----------------
__global__ void conv_silu_kernel(const float* __restrict__ uz, const float* __restrict__ cw,
                                 const float* __restrict__ cb, float* __restrict__ u) {
    int idx = blockIdx.x * blockDim.x + threadIdx.x;
    if (idx >= BLR * EE) return;
    int e = idx % EE;
    int bl = idx / EE;
    int l = bl % LLEN;
    const float* up = uz + (size_t)(bl - l) * (2 * EE) + e;
    float a = cb[e];
#pragma unroll
    for (int k = 0; k < CKW; k++) {
        int lp = l - (CKW - 1) + k;
        if (lp >= 0) a = fmaf(up[(size_t)lp * (2 * EE)], cw[e * CKW + k], a);
    }
    u[idx] = a / (1.f + __expf(-a));
}

// ---------------- selective scan, unrolled x4 with batched loads -----------
__global__ void scan_kernel(const float* __restrict__ u, const float* __restrict__ delta,
                            const float* __restrict__ uz, const float* __restrict__ dbc,
                            const float* __restrict__ A_log, const float* __restrict__ Dsk,
                            __half* __restrict__ y) {
    int w = (blockIdx.x * blockDim.x + threadIdx.x) >> 5;
    int lane = threadIdx.x & 31;
    if (w >= BB * EE / 2) return;
    int b = w / (EE / 2);
    int e = (w - b * (EE / 2)) * 2 + (lane >> 4);
    int s = lane & 15;

    float Ae = -__expf(A_log[e * SSZ + s]);
    float dskip = Dsk[e];
    const float* dptr = delta + (size_t)b * LLEN * EE + e;
    const float* uptr = u + (size_t)b * LLEN * EE + e;
    const float* zptr = uz + (size_t)b * LLEN * 2 * EE + EE + e;
    const float* bc = dbc + (size_t)b * LLEN * 96;
    __half* yptr = y + (size_t)b * LLEN * EE + e;

    float hs = 0.f;
    for (int l0 = 0; l0 < LLEN; l0 += 4) {
        float dlt[4], ul[4], Bv[4], Cv[4], zz[4];
#pragma unroll
        for (int i = 0; i < 4; i++) dlt[i] = dptr[(size_t)(l0 + i) * EE];
#pragma unroll
        for (int i = 0; i < 4; i++) ul[i] = uptr[(size_t)(l0 + i) * EE];
#pragma unroll
        for (int i = 0; i < 4; i++) Bv[i] = bc[(l0 + i) * 96 + RRK + s];
#pragma unroll
        for (int i = 0; i < 4; i++) Cv[i] = bc[(l0 + i) * 96 + RRK + SSZ + s];
#pragma unroll
        for (int i = 0; i < 4; i++) zz[i] = zptr[(size_t)(l0 + i) * 2 * EE];

        float da[4];
#pragma unroll
        for (int i = 0; i < 4; i++) da[i] = __expf(dlt[i] * Ae);

        float p[4];
#pragma unroll
        for (int i = 0; i < 4; i++) {
            hs = fmaf(da[i], hs, (dlt[i] * ul[i]) * Bv[i]);
            p[i] = hs * Cv[i];
        }
#pragma unroll
        for (int i = 0; i < 4; i++) {
            p[i] += __shfl_xor_sync(0xffffffffu, p[i], 8);
            p[i] += __shfl_xor_sync(0xffffffffu, p[i], 4);
            p[i] += __shfl_xor_sync(0xffffffffu, p[i], 2);
            p[i] += __shfl_xor_sync(0xffffffffu, p[i], 1);
        }
        if ((lane & 15) == 0) {
#pragma unroll
            for (int i = 0; i < 4; i++) {
                float sz = zz[i] / (1.f + __expf(-zz[i]));
                yptr[(size_t)(l0 + i) * EE] = __float2half_rn((p[i] + ul[i] * dskip) * sz);
            }
        }
    }
}

// ---------------- reward-weight reduction ----------------
__global__ void wmean_kernel(const float* __restrict__ W_rw, const float* __restrict__ b_rw,
                             float* __restrict__ wm) {
    int d = blockIdx.x * blockDim.x + threadIdx.x;
    if (d < DD) {
        float sum = 0.f;
#pragma unroll
        for (int j = 0; j < SSZ; j++) sum += W_rw[d * SSZ + j];
        wm[d] = sum * (1.f / SSZ);
    }
    if (d == 0) {
        float sum = 0.f;
#pragma unroll
        for (int j = 0; j < SSZ; j++) sum += b_rw[j];
        wm[DD] = sum * (1.f / SSZ);
    }
}

// ---------------- host orchestration ----------------
extern "C" void kernel_launch(void* const* d_in, const int* in_sizes, int n_in,
                              void* d_out, int out_size) {
    const int* x = (const int*)d_in[0];
    const float* mask = (const float*)d_in[1];
    const float* emb = (const float*)d_in[2];
    const float* norm_w = (const float*)d_in[3];
    const float* W_in = (const float*)d_in[4];
    const float* conv_w = (const float*)d_in[5];
    const float* conv_b = (const float*)d_in[6];
    const float* W_x = (const float*)d_in[7];
    const float* W_dt = (const float*)d_in[8];
    const float* b_dt = (const float*)d_in[9];
    const float* A_log = (const float*)d_in[10];
    const float* D_skip = (const float*)d_in[11];
    const float* W_out = (const float*)d_in[12];
    const float* W_rw = (const float*)d_in[13];
    const float* b_rw = (const float*)d_in[14];
    const float* ln_g = (const float*)d_in[15];
    const float* ln_b = (const float*)d_in[16];
    const float* head_W = (const float*)d_in[17];
    float* out = (float*)d_out;

    float *h_, *uz_, *u_, *dbc_, *dbcp_, *delta_, *wm_;
    __half *xnh_, *yh_, *drh_, *winh_, *wouth_, *wdth_, *headh_;
    cudaGetSymbolAddress((void**)&h_, g_h);
    cudaGetSymbolAddress((void**)&uz_, g_uz);
    cudaGetSymbolAddress((void**)&u_, g_u);
    cudaGetSymbolAddress((void**)&dbc_, g_dbc);
    cudaGetSymbolAddress((void**)&dbcp_, g_dbc_part);
    cudaGetSymbolAddress((void**)&delta_, g_delta);
    cudaGetSymbolAddress((void**)&wm_, g_wm);
    cudaGetSymbolAddress((void**)&xnh_, g_xn_h);
    cudaGetSymbolAddress((void**)&yh_, g_y_h);
    cudaGetSymbolAddress((void**)&drh_, g_dr_h);
    cudaGetSymbolAddress((void**)&winh_, g_win_h);
    cudaGetSymbolAddress((void**)&wouth_, g_wout_h);
    cudaGetSymbolAddress((void**)&wdth_, g_wdt_h);
    cudaGetSymbolAddress((void**)&headh_, g_head_h);

    cudaFuncSetAttribute(hgemm<128, 0>, cudaFuncAttributeMaxDynamicSharedMemorySize, HG_SMEM_128);
    cudaFuncSetAttribute(hgemm<128, 2>, cudaFuncAttributeMaxDynamicSharedMemorySize, HG_SMEM_128);
    cudaFuncSetAttribute(hgemm<64, 1>, cudaFuncAttributeMaxDynamicSharedMemorySize, HG_SMEM_64);

    // convert weights to fp16 scratch
    {
        int n4 = NLAY * DD * 2 * EE / 4;
        f2h_kernel<<<(n4 + 255) / 256, 256>>>(W_in, winh_, n4);
        n4 = NLAY * EE * DD / 4;
        f2h_kernel<<<(n4 + 255) / 256, 256>>>(W_out, wouth_, n4);
        n4 = NLAY * RRK * EE / 4;
        f2h_kernel<<<(n4 + 255) / 256, 256>>>(W_dt, wdth_, n4);
        n4 = DD * VV / 4;
        f2h_kernel<<<(n4 + 255) / 256, 256>>>(head_W, headh_, n4);
    }

    embed_kernel<<<BLR, 256>>>(x, mask, emb, h_);
    rmsnorm_kernel<<<BLR, 256>>>(h_, norm_w, xnh_);

    for (int i = 0; i < NLAY; i++) {
        // uz = xn @ W_in   (2048 x 4096 x 1024)  [fp16 mma, BN=128]
        {
            dim3 g(BLR / 128, (2 * EE) / 128);
            hgemm<128, 0><<<g, 256, HG_SMEM_128>>>(xnh_, winh_ + (size_t)i * DD * 2 * EE,
                                                   nullptr, uz_, 2 * EE, DD);
        }

        conv_silu_kernel<<<(BLR * EE) / 256, 256>>>(uz_, conv_w + (size_t)i * EE * CKW,
                                                    conv_b + (size_t)i * EE, u_);

        // dbc = u @ W_x    (2048 x 96 x 2048)  [fp32 split-K x8] -> dbc f32 + dr fp16
        {
            dim3 g(BLR / 128, KSPL);
            wx_splitk_kernel<<<g, 256>>>(u_, W_x + (size_t)i * EE * 96, dbcp_);
            dbc_reduce_kernel<<<(BLR * 96) / 256, 256>>>(dbcp_, dbc_, drh_);
        }

        // delta = softplus(dr @ W_dt + b_dt)  (2048 x 2048 x 64)  [fp16 mma, softplus epi]
        {
            dim3 g(BLR / 128, EE / 128);
            hgemm<128, 2><<<g, 256, HG_SMEM_128>>>(drh_, wdth_ + (size_t)i * RRK * EE,
                                                   b_dt + (size_t)i * EE, delta_, EE, RRK);
        }

        // selective scan + D skip + SiLU gate -> y (fp16)
        scan_kernel<<<(BB * EE / 2) * 32 / 256, 256>>>(u_, delta_, uz_, dbc_,
                                                       A_log + (size_t)i * EE * SSZ,
                                                       D_skip + (size_t)i * EE, yh_);

        // h += y @ W_out   (2048 x 1024 x 2048)  [fp16 mma, BN=64]
        {
            dim3 g(BLR / 128, DD / 64);
            hgemm<64, 1><<<g, 256, HG_SMEM_64>>>(yh_, wouth_ + (size_t)i * EE * DD,
                                                 nullptr, h_, DD, EE);
        }

        // reward scaling fused with next normalization
        wmean_kernel<<<DD / 256, 256>>>(W_rw + (size_t)i * DD * SSZ,
                                        b_rw + (size_t)i * SSZ, wm_);
        if (i < NLAY - 1) {
            rowscale_rms_kernel<<<BLR, 256>>>(h_, wm_, norm_w + (size_t)(i + 1) * DD, xnh_);
        } else {
            rowscale_ln_kernel<<<BLR, 256>>>(h_, wm_, ln_g, ln_b, xnh_);
        }
    }

    // logits = xn @ head_W  (2048 x 32000 x 1024)  [fp16 mma, BN=128]
    {
        dim3 g(BLR / 128, VV / 128);
        hgemm<128, 0><<<g, 256, HG_SMEM_128>>>(xnh_, headh_, nullptr, out, VV, DD);
    }
}